// round 14
// baseline (speedup 1.0000x reference)
#include <cuda_runtime.h>
#include <cuda_bf16.h>
#include <math.h>
#include <stdint.h>

#define Bb 1024
#define Nn 11
#define Ff 512
#define ZI 10
#define PPF 66
#define R0 (Bb*PPF)
#define R1 (Bb*Nn)
#define G3 1536

#define KC 32
#define NCHUNK (Ff/KC)          /* 16 */
#define SSTR 40                 /* bf16 elems per smem row (32 data + 8 pad) */
#define PL 10240                /* bytes per plane: 128*40*2 */
#define ST (4*PL)               /* bytes per stage = 40KB */
#define DSMEM (2*ST)            /* 81920 */
#define NT 512                  /* threads per GEMM CTA */

/* ------------------------------------------------------------------ */
__device__ __forceinline__ uint32_t smaddr(const void* p) {
    uint32_t a;
    asm("{ .reg .u64 t; cvta.to.shared.u64 t, %1; cvt.u32.u64 %0, t; }"
        : "=r"(a) : "l"(p));
    return a;
}
__device__ __forceinline__ void ldm4(uint32_t a, uint32_t* r) {
    asm volatile("ldmatrix.sync.aligned.m8n8.x4.shared.b16 {%0,%1,%2,%3}, [%4];"
                 : "=r"(r[0]), "=r"(r[1]), "=r"(r[2]), "=r"(r[3]) : "r"(a));
}
__device__ __forceinline__ void mma16816(float* d, const uint32_t* a, uint32_t b0, uint32_t b1) {
    asm volatile(
        "mma.sync.aligned.m16n8k16.row.col.f32.bf16.bf16.f32 "
        "{%0,%1,%2,%3},{%4,%5,%6,%7},{%8,%9},{%0,%1,%2,%3};"
        : "+f"(d[0]), "+f"(d[1]), "+f"(d[2]), "+f"(d[3])
        : "r"(a[0]), "r"(a[1]), "r"(a[2]), "r"(a[3]), "r"(b0), "r"(b1));
}
__device__ __forceinline__ void split1(float v, unsigned short& h, unsigned short& l) {
    __nv_bfloat16 bh = __float2bfloat16_rn(v);
    float r = v - __bfloat162float(bh);
    __nv_bfloat16 bl = __float2bfloat16_rn(r);
    h = *(unsigned short*)&bh;
    l = *(unsigned short*)&bl;
}

/* ------------------------------------------------------------------ */
__constant__ int c_pi[66] = {
  0,0,0,0,0,0,0,0,0,0,0, 1,1,1,1,1,1,1,1,1,1, 2,2,2,2,2,2,2,2,2,
  3,3,3,3,3,3,3,3, 4,4,4,4,4,4,4, 5,5,5,5,5,5, 6,6,6,6,6, 7,7,7,7, 8,8,8, 9,9, 10};
__constant__ int c_pj[66] = {
  0,1,2,3,4,5,6,7,8,9,10, 1,2,3,4,5,6,7,8,9,10, 2,3,4,5,6,7,8,9,10,
  3,4,5,6,7,8,9,10, 4,5,6,7,8,9,10, 5,6,7,8,9,10, 6,7,8,9,10, 7,8,9,10, 8,9,10, 9,10, 10};

/* f32 scratch */
__device__ float g_colA[Bb * Ff];
__device__ float g_colB[Bb * Ff];
__device__ float g_az[Bb * 12];
__device__ float g_mb[Bb * Ff];
__device__ float g_gi[Bb * G3];
__device__ float g_gh[Bb * G3];

/* pre-split bf16 operand planes (hi/lo) */
__device__ unsigned short g_W1h[Ff * Ff],  g_W1l[Ff * Ff];
__device__ unsigned short g_W2h[Ff * Ff],  g_W2l[Ff * Ff];
__device__ unsigned short g_Wihh[G3 * Ff], g_Wihl[G3 * Ff];
__device__ unsigned short g_Whhh[G3 * Ff], g_Whhl[G3 * Ff];
__device__ unsigned short g_Eh[R0 * Ff],   g_El[R0 * Ff];
__device__ unsigned short g_H1h[R0 * Ff],  g_H1l[R0 * Ff];
__device__ unsigned short g_czh[Bb * Ff],  g_czl[Bb * Ff];
__device__ unsigned short g_mzh[Bb * Ff],  g_mzl[Bb * Ff];

__device__ __forceinline__ float* colptr(int sel) { return sel ? g_colB : g_colA; }

/* ------------------------------------------------------------------ */
/* one 32-K chunk, warp tile 32x32: 2 k16-steps, per np (2) 12 MMAs. */
__device__ __forceinline__ void gemm_chunk2(uint32_t base, int wm, int wn,
                                            int lane, float acc[2][4][4])
{
    const int rsel = lane & 15;
    const int ksel = (lane >> 4) * 8;
#pragma unroll
    for (int s = 0; s < 2; s++) {
        uint32_t ah[2][4], al[2][4];
#pragma unroll
        for (int mt = 0; mt < 2; mt++) {
            uint32_t off = (uint32_t)((wm*32 + mt*16 + rsel) * SSTR + s*16 + ksel) * 2;
            ldm4(base + 0*PL + off, ah[mt]);
            ldm4(base + 1*PL + off, al[mt]);
        }
#pragma unroll
        for (int np = 0; np < 2; np++) {
            uint32_t bh[4], bl[4];
            uint32_t off = (uint32_t)((wn*32 + np*16 + rsel) * SSTR + s*16 + ksel) * 2;
            ldm4(base + 2*PL + off, bh);
            ldm4(base + 3*PL + off, bl);
#pragma unroll
            for (int mt = 0; mt < 2; mt++)
#pragma unroll
                for (int h = 0; h < 2; h++) {
                    const int nt = np*2 + h;
                    mma16816(acc[mt][nt], ah[mt], bh[h], bh[h+2]);
                    mma16816(acc[mt][nt], ah[mt], bl[h], bl[h+2]);
                    mma16816(acc[mt][nt], al[mt], bh[h], bh[h+2]);
                }
        }
    }
}

/* double-buffered cp.async mainloop over K=512 (512 threads).
   Each thread stages 4 x 16B: one unit (row, q) in each of the 4 planes. */
__device__ __forceinline__ void gemm_pipe(
    const unsigned short* __restrict__ Ah, const unsigned short* __restrict__ Al,
    const unsigned short* __restrict__ Bh, const unsigned short* __restrict__ Bl,
    char* dsm, int tid, float acc[2][4][4])
{
    const uint32_t sb = smaddr(dsm);
    const int lane = tid & 31, wid = tid >> 5;
    const int wm = wid & 3, wn = wid >> 2;

    const int q  = tid & 3;
    const int r0 = tid >> 2;               /* 0..127 */
    const unsigned short* pg[4] = { Ah, Al, Bh, Bl };
    const int go = r0 * Ff + q * 8;
    const uint32_t so = (uint32_t)(r0 * SSTR + q * 8) * 2;

    auto stg = [&](int c, int s) {
        uint32_t db = sb + (uint32_t)s * ST + so;
        const int ke = c * KC + go;
#pragma unroll
        for (int pl = 0; pl < 4; pl++)
            asm volatile("cp.async.ca.shared.global [%0],[%1],16;"
                         :: "r"(db + (uint32_t)pl * PL), "l"(pg[pl] + ke) : "memory");
        asm volatile("cp.async.commit_group;" ::: "memory");
    };

    stg(0, 0);
    asm volatile("cp.async.wait_group 0;" ::: "memory");
    __syncthreads();
    for (int c = 0; c < NCHUNK; c++) {
        if (c + 1 < NCHUNK) stg(c + 1, (c + 1) & 1);
        gemm_chunk2(sb + (uint32_t)(c & 1) * ST, wm, wn, lane, acc);
        if (c + 1 < NCHUNK) asm volatile("cp.async.wait_group 0;" ::: "memory");
        __syncthreads();
    }
}

/* ------------------------------------------------------------------ */
#define W1_E (Ff*Ff)
#define WIH_E (G3*Ff)
__global__ void k_split_all(const float* __restrict__ W1, const float* __restrict__ W2,
                            const float* __restrict__ Wih, const float* __restrict__ Whh)
{
    int i4 = (blockIdx.x * 256 + threadIdx.x) * 4;
    const float* src;
    unsigned short *dh, *dl;
    int o;
    if (i4 < W1_E)               { src = W1;  dh = g_W1h;  dl = g_W1l;  o = i4; }
    else if (i4 < 2*W1_E)        { src = W2;  dh = g_W2h;  dl = g_W2l;  o = i4 - W1_E; }
    else if (i4 < 2*W1_E+WIH_E)  { src = Wih; dh = g_Wihh; dl = g_Wihl; o = i4 - 2*W1_E; }
    else                         { src = Whh; dh = g_Whhh; dl = g_Whhl; o = i4 - 2*W1_E - WIH_E; }
    float4 v = *(const float4*)(src + o);
    ushort4 h, l;
    split1(v.x, h.x, l.x); split1(v.y, h.y, l.y);
    split1(v.z, h.z, l.z); split1(v.w, h.w, l.w);
    *(ushort4*)(dh + o) = h;
    *(ushort4*)(dl + o) = l;
}

/* E rows: E[r][f] = x_i[f]*x_j[f], pre-split. t0: zidx column read from nf */
__global__ void k_egen(const float* __restrict__ nf, int colsel, int ppb, int full, int t0)
{
    int t4 = blockIdx.x * 256 + threadIdx.x;
    int r = t4 >> 7, q = t4 & 127;
    int b = r / ppb, p = r - b * ppb;
    int i, j;
    if (full) { i = c_pi[p]; j = c_pj[p]; } else { i = p; j = ZI; }
    const float* colb = t0 ? (nf + (size_t)(b * Nn + ZI) * Ff)
                           : (colptr(colsel) + (size_t)b * Ff);
    const float* xi = (i == ZI) ? colb : (nf + (size_t)(b * Nn + i) * Ff);
    const float* xj = (j == ZI) ? colb : (nf + (size_t)(b * Nn + j) * Ff);
    float4 a = *(const float4*)(xi + q * 4);
    float4 c2 = *(const float4*)(xj + q * 4);
    ushort4 h, l;
    split1(a.x * c2.x, h.x, l.x);
    split1(a.y * c2.y, h.y, l.y);
    split1(a.z * c2.z, h.z, l.z);
    split1(a.w * c2.w, h.w, l.w);
    size_t o = (size_t)r * Ff + q * 4;
    *(ushort4*)(g_Eh + o) = h;
    *(ushort4*)(g_El + o) = l;
}

/* ------------------------------------------------------------------ */
/* K1: H1 = relu(E @ W1^T + b1), output pre-split */
__global__ __launch_bounds__(NT, 2)
void k_mlp1(const float* __restrict__ b1)
{
    extern __shared__ char dsm[];
    const int tid = threadIdx.x, lane = tid & 31, wid = tid >> 5;
    const int wm = wid & 3, wn = wid >> 2;
    const int rb = blockIdx.x, cb = blockIdx.y;

    float acc[2][4][4];
#pragma unroll
    for (int a = 0; a < 2; a++)
#pragma unroll
        for (int b = 0; b < 4; b++)
#pragma unroll
            for (int c = 0; c < 4; c++) acc[a][b][c] = 0.f;

    gemm_pipe(g_Eh + (size_t)rb * 128 * Ff, g_El + (size_t)rb * 128 * Ff,
              g_W1h + (size_t)cb * 128 * Ff, g_W1l + (size_t)cb * 128 * Ff,
              dsm, tid, acc);

    const int r0 = rb * 128 + wm * 32 + (lane >> 2);
    const int c0 = cb * 128 + wn * 32 + (lane & 3) * 2;
#pragma unroll
    for (int mt = 0; mt < 2; mt++)
#pragma unroll
        for (int nt = 0; nt < 4; nt++) {
            const int cc = c0 + nt * 8;
            const float bx = b1[cc], by = b1[cc + 1];
#pragma unroll
            for (int hh = 0; hh < 2; hh++) {
                const int rr = r0 + mt * 16 + hh * 8;
                float v0 = fmaxf(acc[mt][nt][hh*2+0] + bx, 0.f);
                float v1 = fmaxf(acc[mt][nt][hh*2+1] + by, 0.f);
                ushort2 h, l;
                split1(v0, h.x, l.x);
                split1(v1, h.y, l.y);
                *(ushort2*)(g_H1h + (size_t)rr * Ff + cc) = h;
                *(ushort2*)(g_H1l + (size_t)rr * Ff + cc) = l;
            }
        }
}

/* ------------------------------------------------------------------ */
/* K2: adj = sum_g wout[g]*relu((H1 @ W2^T)+b2) + bout */
__global__ __launch_bounds__(NT, 2)
void k_mlp2(const float* __restrict__ b2, const float* __restrict__ wout,
            const float* __restrict__ boutp, float* __restrict__ adj,
            int ppb, int full)
{
    extern __shared__ char dsm[];
    __shared__ float red[128][4];

    const int tid = threadIdx.x, lane = tid & 31, wid = tid >> 5;
    const int wm = wid & 3, wn = wid >> 2;
    const int rb = blockIdx.x;

    float part[2][2] = {{0.f, 0.f}, {0.f, 0.f}};

    for (int gc = 0; gc < 4; gc++) {
        float acc[2][4][4];
#pragma unroll
        for (int a = 0; a < 2; a++)
#pragma unroll
            for (int b = 0; b < 4; b++)
#pragma unroll
                for (int c = 0; c < 4; c++) acc[a][b][c] = 0.f;

        gemm_pipe(g_H1h + (size_t)rb * 128 * Ff, g_H1l + (size_t)rb * 128 * Ff,
                  g_W2h + (size_t)gc * 128 * Ff, g_W2l + (size_t)gc * 128 * Ff,
                  dsm, tid, acc);
        __syncthreads();   /* smem reuse across gc iterations */

        const int c0 = gc * 128 + wn * 32 + (lane & 3) * 2;
#pragma unroll
        for (int mt = 0; mt < 2; mt++)
#pragma unroll
            for (int nt = 0; nt < 4; nt++) {
                const int cc = c0 + nt * 8;
                const float bx = b2[cc], by = b2[cc + 1];
                const float wx = wout[cc], wy = wout[cc + 1];
                part[mt][0] += fmaxf(acc[mt][nt][0] + bx, 0.f) * wx
                             + fmaxf(acc[mt][nt][1] + by, 0.f) * wy;
                part[mt][1] += fmaxf(acc[mt][nt][2] + bx, 0.f) * wx
                             + fmaxf(acc[mt][nt][3] + by, 0.f) * wy;
            }
    }

#pragma unroll
    for (int mt = 0; mt < 2; mt++)
#pragma unroll
        for (int h = 0; h < 2; h++) {
            float v = part[mt][h];
            v += __shfl_xor_sync(0xffffffffu, v, 1);
            v += __shfl_xor_sync(0xffffffffu, v, 2);
            part[mt][h] = v;
        }
    if ((lane & 3) == 0) {
#pragma unroll
        for (int mt = 0; mt < 2; mt++)
#pragma unroll
            for (int h = 0; h < 2; h++)
                red[wm * 32 + mt * 16 + h * 8 + (lane >> 2)][wn] = part[mt][h];
    }
    __syncthreads();

    if (tid < 128) {
        float s = red[tid][0] + red[tid][1] + red[tid][2] + red[tid][3] + boutp[0];
        int gr = rb * 128 + tid;
        int b = gr / ppb, p = gr - b * ppb;
        int i, j;
        if (full) { i = c_pi[p]; j = c_pj[p]; } else { i = p; j = ZI; }
        adj[b * 121 + i * 11 + j] = s;
        adj[b * 121 + j * 11 + i] = s;
    }
}

/* ------------------------------------------------------------------ */
/* fused: softmax(adj[b,ZI,:]) + m_base + cur/m_z splits (+ col init at t0) */
__global__ void k_attn(const float* __restrict__ nf, const float* __restrict__ adj,
                       int colsel, int t0)
{
    __shared__ float a_sh[11];
    __shared__ float azz_s;

    const int b = blockIdx.x, ch = blockIdx.y, tid = threadIdx.x;

    if (tid < 32) {
        float v = (tid < 11) ? adj[b * 121 + ZI * 11 + tid] : -1e30f;
        float m = v;
#pragma unroll
        for (int o = 16; o > 0; o >>= 1) m = fmaxf(m, __shfl_xor_sync(0xffffffffu, m, o));
        float e = (tid < 11) ? expf(v - m) : 0.f;
        float s = e;
#pragma unroll
        for (int o = 16; o > 0; o >>= 1) s += __shfl_xor_sync(0xffffffffu, s, o);
        float a = e / s;
        if (tid < 11) a_sh[tid] = a;
        if (tid == ZI) azz_s = a;
        if (ch == 0) {
            if (tid < 11) g_az[b * 12 + tid] = a;
            if (tid == ZI) g_az[b * 12 + 11] = a;
        }
    }
    __syncthreads();

    const int f = ch * 128 + tid;
    const int idx = b * Ff + f;
    float mb = 0.f;
#pragma unroll
    for (int j = 0; j < 10; j++)
        mb += a_sh[j] * nf[(size_t)(b * Nn + j) * Ff + f];
    g_mb[idx] = mb;

    float cur = t0 ? nf[(size_t)(b * Nn + ZI) * Ff + f] : colptr(colsel)[idx];
    if (t0) colptr(colsel)[idx] = cur;
    float mz = mb + azz_s * cur;
    split1(cur, g_czh[idx], g_czl[idx]);
    split1(mz,  g_mzh[idx], g_mzl[idx]);
}

/* ------------------------------------------------------------------ */
/* K5: gi = m_z @ W_ih^T (z=0) ; gh = cur @ W_hh^T (z=1) */
__global__ __launch_bounds__(NT, 2)
void k_gru(void)
{
    extern __shared__ char dsm[];
    const int tid = threadIdx.x, lane = tid & 31, wid = tid >> 5;
    const int wm = wid & 3, wn = wid >> 2;
    const int rb = blockIdx.x, cb = blockIdx.y, wh = blockIdx.z;

    const unsigned short* Ah = (wh ? g_czh : g_mzh) + (size_t)rb * 128 * Ff;
    const unsigned short* Al = (wh ? g_czl : g_mzl) + (size_t)rb * 128 * Ff;
    const unsigned short* Bh = (wh ? g_Whhh : g_Wihh) + (size_t)cb * 128 * Ff;
    const unsigned short* Bl = (wh ? g_Whhl : g_Wihl) + (size_t)cb * 128 * Ff;
    float* out = wh ? g_gh : g_gi;

    float acc[2][4][4];
#pragma unroll
    for (int a = 0; a < 2; a++)
#pragma unroll
        for (int b = 0; b < 4; b++)
#pragma unroll
            for (int c = 0; c < 4; c++) acc[a][b][c] = 0.f;

    gemm_pipe(Ah, Al, Bh, Bl, dsm, tid, acc);

    const int r0 = rb * 128 + wm * 32 + (lane >> 2);
    const int c0 = cb * 128 + wn * 32 + (lane & 3) * 2;
#pragma unroll
    for (int mt = 0; mt < 2; mt++)
#pragma unroll
        for (int nt = 0; nt < 4; nt++) {
            const int cc = c0 + nt * 8;
            const int rr = r0 + mt * 16;
            *(float2*)(out + (size_t)rr * G3 + cc)       = make_float2(acc[mt][nt][0], acc[mt][nt][1]);
            *(float2*)(out + (size_t)(rr + 8) * G3 + cc) = make_float2(acc[mt][nt][2], acc[mt][nt][3]);
        }
}

/* ------------------------------------------------------------------ */
/* GRU gates; produce next-step splits, or write final output directly */
__global__ void k_gate(int colsel, float* __restrict__ dst, int final_step)
{
    int idx = blockIdx.x * 256 + threadIdx.x;
    int b = idx >> 9, f = idx & 511;
    const float* cur = colptr(colsel);
    float* nxt = colptr(1 - colsel);
    const float* gib = g_gi + b * G3;
    const float* ghb = g_gh + b * G3;
    float ir = gib[f],         hr = ghb[f];
    float iz = gib[512 + f],   hz = ghb[512 + f];
    float in_ = gib[1024 + f], hn = ghb[1024 + f];
    float rr = 1.f / (1.f + expf(-(ir + hr)));
    float zz = 1.f / (1.f + expf(-(iz + hz)));
    float nn = tanhf(in_ + rr * hn);
    float h = cur[idx];
    float v = (1.f - zz) * nn + zz * h;
    nxt[idx] = v;
    if (final_step) {
        dst[idx] = v;
    } else {
        float az = g_az[b * 12 + 11];
        float mz = g_mb[idx] + az * v;
        split1(v,  g_czh[idx], g_czl[idx]);
        split1(mz, g_mzh[idx], g_mzl[idx]);
    }
}

/* ------------------------------------------------------------------ */
extern "C" void kernel_launch(void* const* d_in, const int* in_sizes, int n_in,
                              void* d_out, int out_size)
{
    const float* nf  = (const float*)d_in[0];
    const float* W1  = (const float*)d_in[1];
    const float* b1  = (const float*)d_in[2];
    const float* W2  = (const float*)d_in[3];
    const float* b2  = (const float*)d_in[4];
    const float* wo  = (const float*)d_in[5];
    const float* bo  = (const float*)d_in[6];
    const float* Wih = (const float*)d_in[7];
    const float* Whh = (const float*)d_in[8];

    float* adj    = (float*)d_out;
    float* colout = (float*)d_out + Bb * 121;

    cudaFuncSetAttribute(k_mlp1, cudaFuncAttributeMaxDynamicSharedMemorySize, DSMEM);
    cudaFuncSetAttribute(k_mlp2, cudaFuncAttributeMaxDynamicSharedMemorySize, DSMEM);
    cudaFuncSetAttribute(k_gru,  cudaFuncAttributeMaxDynamicSharedMemorySize, DSMEM);

    k_split_all<<<(2 * W1_E + 2 * WIH_E) / 1024, 256>>>(W1, W2, Wih, Whh);

    int sel = 0;
    for (int t = 0; t < 3; t++) {
        const int rows = (t == 0) ? R0 : R1;
        const int ppb  = (t == 0) ? PPF : Nn;
        const int full = (t == 0) ? 1 : 0;
        const int t0   = (t == 0) ? 1 : 0;
        k_egen<<<(rows * (Ff / 4)) / 256, 256>>>(nf, sel, ppb, full, t0);
        k_mlp1<<<dim3(rows / 128, 4), NT, DSMEM>>>(b1);
        k_mlp2<<<rows / 128, NT, DSMEM>>>(b2, wo, bo, adj, ppb, full);
        k_attn<<<dim3(Bb, 4), 128>>>(nf, adj, sel, t0);
        for (int s = 0; s < 3; s++) {
            const int fin = (t == 2 && s == 2) ? 1 : 0;
            k_gru<<<dim3(Bb / 128, G3 / 128, 2), NT, DSMEM>>>();
            k_gate<<<(Bb * Ff) / 256, 256>>>(sel, colout, fin);
            sel = 1 - sel;
        }
    }
}

// round 15
// speedup vs baseline: 1.1371x; 1.1371x over previous
#include <cuda_runtime.h>
#include <cuda_bf16.h>
#include <math.h>
#include <stdint.h>

#define Bb 1024
#define Nn 11
#define Ff 512
#define ZI 10
#define PPF 66
#define R0 (Bb*PPF)
#define R1 (Bb*Nn)
#define G3 1536

#define KC 32
#define NCHUNK (Ff/KC)          /* 16 */
#define SSTR 40                 /* bf16 elems per smem row (32 data + 8 pad) */
#define PL 10240                /* bytes per plane: 128*40*2 */
#define ST (4*PL)               /* bytes per stage = 40KB */
#define DSMEM (2*ST)            /* 81920 */

/* ------------------------------------------------------------------ */
__device__ __forceinline__ uint32_t smaddr(const void* p) {
    uint32_t a;
    asm("{ .reg .u64 t; cvta.to.shared.u64 t, %1; cvt.u32.u64 %0, t; }"
        : "=r"(a) : "l"(p));
    return a;
}
__device__ __forceinline__ void ldm4(uint32_t a, uint32_t* r) {
    asm volatile("ldmatrix.sync.aligned.m8n8.x4.shared.b16 {%0,%1,%2,%3}, [%4];"
                 : "=r"(r[0]), "=r"(r[1]), "=r"(r[2]), "=r"(r[3]) : "r"(a));
}
__device__ __forceinline__ void mma16816(float* d, const uint32_t* a, uint32_t b0, uint32_t b1) {
    asm volatile(
        "mma.sync.aligned.m16n8k16.row.col.f32.bf16.bf16.f32 "
        "{%0,%1,%2,%3},{%4,%5,%6,%7},{%8,%9},{%0,%1,%2,%3};"
        : "+f"(d[0]), "+f"(d[1]), "+f"(d[2]), "+f"(d[3])
        : "r"(a[0]), "r"(a[1]), "r"(a[2]), "r"(a[3]), "r"(b0), "r"(b1));
}
__device__ __forceinline__ void split1(float v, unsigned short& h, unsigned short& l) {
    __nv_bfloat16 bh = __float2bfloat16_rn(v);
    float r = v - __bfloat162float(bh);
    __nv_bfloat16 bl = __float2bfloat16_rn(r);
    h = *(unsigned short*)&bh;
    l = *(unsigned short*)&bl;
}

/* ------------------------------------------------------------------ */
__constant__ int c_pi[66] = {
  0,0,0,0,0,0,0,0,0,0,0, 1,1,1,1,1,1,1,1,1,1, 2,2,2,2,2,2,2,2,2,
  3,3,3,3,3,3,3,3, 4,4,4,4,4,4,4, 5,5,5,5,5,5, 6,6,6,6,6, 7,7,7,7, 8,8,8, 9,9, 10};
__constant__ int c_pj[66] = {
  0,1,2,3,4,5,6,7,8,9,10, 1,2,3,4,5,6,7,8,9,10, 2,3,4,5,6,7,8,9,10,
  3,4,5,6,7,8,9,10, 4,5,6,7,8,9,10, 5,6,7,8,9,10, 6,7,8,9,10, 7,8,9,10, 8,9,10, 9,10, 10};

/* f32 scratch */
__device__ float g_colA[Bb * Ff];
__device__ float g_colB[Bb * Ff];
__device__ float g_az[Bb * 12];
__device__ float g_mb[Bb * Ff];
__device__ float g_gi[Bb * G3];
__device__ float g_gh[Bb * G3];

/* pre-split bf16 operand planes (hi/lo) */
__device__ unsigned short g_W1h[Ff * Ff],  g_W1l[Ff * Ff];
__device__ unsigned short g_W2h[Ff * Ff],  g_W2l[Ff * Ff];
__device__ unsigned short g_Wihh[G3 * Ff], g_Wihl[G3 * Ff];
__device__ unsigned short g_Whhh[G3 * Ff], g_Whhl[G3 * Ff];
__device__ unsigned short g_Eh[R0 * Ff],   g_El[R0 * Ff];
__device__ unsigned short g_H1h[R0 * Ff],  g_H1l[R0 * Ff];
__device__ unsigned short g_czh[Bb * Ff],  g_czl[Bb * Ff];
__device__ unsigned short g_mzh[Bb * Ff],  g_mzl[Bb * Ff];

__device__ __forceinline__ float* colptr(int sel) { return sel ? g_colB : g_colA; }

/* ------------------------------------------------------------------ */
/* one 32-K chunk: 2 k16-steps. Within each np the 12 MMAs are issued
   TERM-MAJOR (hh, hl, lh), so each accumulator is revisited only every
   4 MMAs instead of back-to-back -> breaks the serial HMMA chains.
   Per-acc term order unchanged -> bit-identical results. */
__device__ __forceinline__ void gemm_chunk2(uint32_t base, int wm, int wn,
                                            int lane, float acc[2][8][4])
{
    const int rsel = lane & 15;
    const int ksel = (lane >> 4) * 8;
#pragma unroll
    for (int s = 0; s < 2; s++) {
        uint32_t ah[2][4], al[2][4];
#pragma unroll
        for (int mt = 0; mt < 2; mt++) {
            uint32_t off = (uint32_t)((wm*32 + mt*16 + rsel) * SSTR + s*16 + ksel) * 2;
            ldm4(base + 0*PL + off, ah[mt]);
            ldm4(base + 1*PL + off, al[mt]);
        }
#pragma unroll
        for (int np = 0; np < 4; np++) {
            uint32_t bh[4], bl[4];
            uint32_t off = (uint32_t)((wn*64 + np*16 + rsel) * SSTR + s*16 + ksel) * 2;
            ldm4(base + 2*PL + off, bh);
            ldm4(base + 3*PL + off, bl);
            /* term 0: ah * bh */
#pragma unroll
            for (int mt = 0; mt < 2; mt++)
#pragma unroll
                for (int h = 0; h < 2; h++)
                    mma16816(acc[mt][np*2 + h], ah[mt], bh[h], bh[h+2]);
            /* term 1: ah * bl */
#pragma unroll
            for (int mt = 0; mt < 2; mt++)
#pragma unroll
                for (int h = 0; h < 2; h++)
                    mma16816(acc[mt][np*2 + h], ah[mt], bl[h], bl[h+2]);
            /* term 2: al * bh */
#pragma unroll
            for (int mt = 0; mt < 2; mt++)
#pragma unroll
                for (int h = 0; h < 2; h++)
                    mma16816(acc[mt][np*2 + h], al[mt], bh[h], bh[h+2]);
        }
    }
}

/* double-buffered cp.async mainloop over K=512.
   Planes row-major [128][Ff] bf16. Lean addressing: 4 plane ptrs +
   2 row offsets per thread (each thread: 4 planes x 2 rows x 16B). */
__device__ __forceinline__ void gemm_pipe(
    const unsigned short* __restrict__ Ah, const unsigned short* __restrict__ Al,
    const unsigned short* __restrict__ Bh, const unsigned short* __restrict__ Bl,
    char* dsm, int tid, float acc[2][8][4])
{
    const uint32_t sb = smaddr(dsm);
    const int lane = tid & 31, wid = tid >> 5;
    const int wm = wid & 3, wn = wid >> 2;

    const int q8 = (tid & 3) * 8;            /* element offset in row */
    const int r0 = tid >> 2;                 /* rows r0 and r0+64 */
    const unsigned short* pg[4] = { Ah, Al, Bh, Bl };
    const int go0 = r0 * Ff + q8;
    const int go1 = (r0 + 64) * Ff + q8;
    const uint32_t so0 = (uint32_t)(r0 * SSTR + q8) * 2;
    const uint32_t so1 = (uint32_t)((r0 + 64) * SSTR + q8) * 2;

    auto stg = [&](int c, int s) {
        uint32_t db = sb + (uint32_t)s * ST;
        const int ke = c * KC;
#pragma unroll
        for (int pl = 0; pl < 4; pl++) {
            asm volatile("cp.async.ca.shared.global [%0],[%1],16;"
                         :: "r"(db + (uint32_t)pl * PL + so0), "l"(pg[pl] + go0 + ke) : "memory");
            asm volatile("cp.async.ca.shared.global [%0],[%1],16;"
                         :: "r"(db + (uint32_t)pl * PL + so1), "l"(pg[pl] + go1 + ke) : "memory");
        }
        asm volatile("cp.async.commit_group;" ::: "memory");
    };

    stg(0, 0);
    asm volatile("cp.async.wait_group 0;" ::: "memory");
    __syncthreads();
    for (int c = 0; c < NCHUNK; c++) {
        if (c + 1 < NCHUNK) stg(c + 1, (c + 1) & 1);
        gemm_chunk2(sb + (uint32_t)(c & 1) * ST, wm, wn, lane, acc);
        if (c + 1 < NCHUNK) asm volatile("cp.async.wait_group 0;" ::: "memory");
        __syncthreads();
    }
}

/* ------------------------------------------------------------------ */
#define W1_E (Ff*Ff)
#define WIH_E (G3*Ff)
__global__ void k_split_all(const float* __restrict__ W1, const float* __restrict__ W2,
                            const float* __restrict__ Wih, const float* __restrict__ Whh)
{
    int i4 = (blockIdx.x * 256 + threadIdx.x) * 4;
    const float* src;
    unsigned short *dh, *dl;
    int o;
    if (i4 < W1_E)               { src = W1;  dh = g_W1h;  dl = g_W1l;  o = i4; }
    else if (i4 < 2*W1_E)        { src = W2;  dh = g_W2h;  dl = g_W2l;  o = i4 - W1_E; }
    else if (i4 < 2*W1_E+WIH_E)  { src = Wih; dh = g_Wihh; dl = g_Wihl; o = i4 - 2*W1_E; }
    else                         { src = Whh; dh = g_Whhh; dl = g_Whhl; o = i4 - 2*W1_E - WIH_E; }
    float4 v = *(const float4*)(src + o);
    ushort4 h, l;
    split1(v.x, h.x, l.x); split1(v.y, h.y, l.y);
    split1(v.z, h.z, l.z); split1(v.w, h.w, l.w);
    *(ushort4*)(dh + o) = h;
    *(ushort4*)(dl + o) = l;
}

/* E rows: E[r][f] = x_i[f]*x_j[f], pre-split. t0: zidx column read from nf */
__global__ void k_egen(const float* __restrict__ nf, int colsel, int ppb, int full, int t0)
{
    int t4 = blockIdx.x * 256 + threadIdx.x;
    int r = t4 >> 7, q = t4 & 127;
    int b = r / ppb, p = r - b * ppb;
    int i, j;
    if (full) { i = c_pi[p]; j = c_pj[p]; } else { i = p; j = ZI; }
    const float* colb = t0 ? (nf + (size_t)(b * Nn + ZI) * Ff)
                           : (colptr(colsel) + (size_t)b * Ff);
    const float* xi = (i == ZI) ? colb : (nf + (size_t)(b * Nn + i) * Ff);
    const float* xj = (j == ZI) ? colb : (nf + (size_t)(b * Nn + j) * Ff);
    float4 a = *(const float4*)(xi + q * 4);
    float4 c2 = *(const float4*)(xj + q * 4);
    ushort4 h, l;
    split1(a.x * c2.x, h.x, l.x);
    split1(a.y * c2.y, h.y, l.y);
    split1(a.z * c2.z, h.z, l.z);
    split1(a.w * c2.w, h.w, l.w);
    size_t o = (size_t)r * Ff + q * 4;
    *(ushort4*)(g_Eh + o) = h;
    *(ushort4*)(g_El + o) = l;
}

/* ------------------------------------------------------------------ */
/* K1: H1 = relu(E @ W1^T + b1), output pre-split */
__global__ __launch_bounds__(256, 2)
void k_mlp1(const float* __restrict__ b1)
{
    extern __shared__ char dsm[];
    const int tid = threadIdx.x, lane = tid & 31, wid = tid >> 5;
    const int wm = wid & 3, wn = wid >> 2;
    const int rb = blockIdx.x, cb = blockIdx.y;

    float acc[2][8][4];
#pragma unroll
    for (int a = 0; a < 2; a++)
#pragma unroll
        for (int b = 0; b < 8; b++)
#pragma unroll
            for (int c = 0; c < 4; c++) acc[a][b][c] = 0.f;

    gemm_pipe(g_Eh + (size_t)rb * 128 * Ff, g_El + (size_t)rb * 128 * Ff,
              g_W1h + (size_t)cb * 128 * Ff, g_W1l + (size_t)cb * 128 * Ff,
              dsm, tid, acc);

    const int r0 = rb * 128 + wm * 32 + (lane >> 2);
    const int c0 = cb * 128 + wn * 64 + (lane & 3) * 2;
#pragma unroll
    for (int mt = 0; mt < 2; mt++)
#pragma unroll
        for (int nt = 0; nt < 8; nt++) {
            const int cc = c0 + nt * 8;
            const float bx = b1[cc], by = b1[cc + 1];
#pragma unroll
            for (int hh = 0; hh < 2; hh++) {
                const int rr = r0 + mt * 16 + hh * 8;
                float v0 = fmaxf(acc[mt][nt][hh*2+0] + bx, 0.f);
                float v1 = fmaxf(acc[mt][nt][hh*2+1] + by, 0.f);
                ushort2 h, l;
                split1(v0, h.x, l.x);
                split1(v1, h.y, l.y);
                *(ushort2*)(g_H1h + (size_t)rr * Ff + cc) = h;
                *(ushort2*)(g_H1l + (size_t)rr * Ff + cc) = l;
            }
        }
}

/* ------------------------------------------------------------------ */
/* K2: adj = sum_g wout[g]*relu((H1 @ W2^T)+b2) + bout */
__global__ __launch_bounds__(256, 2)
void k_mlp2(const float* __restrict__ b2, const float* __restrict__ wout,
            const float* __restrict__ boutp, float* __restrict__ adj,
            int ppb, int full)
{
    extern __shared__ char dsm[];
    __shared__ float red[128][2];

    const int tid = threadIdx.x, lane = tid & 31, wid = tid >> 5;
    const int wm = wid & 3, wn = wid >> 2;
    const int rb = blockIdx.x;

    float part[2][2] = {{0.f, 0.f}, {0.f, 0.f}};

    for (int gc = 0; gc < 4; gc++) {
        float acc[2][8][4];
#pragma unroll
        for (int a = 0; a < 2; a++)
#pragma unroll
            for (int b = 0; b < 8; b++)
#pragma unroll
                for (int c = 0; c < 4; c++) acc[a][b][c] = 0.f;

        gemm_pipe(g_H1h + (size_t)rb * 128 * Ff, g_H1l + (size_t)rb * 128 * Ff,
                  g_W2h + (size_t)gc * 128 * Ff, g_W2l + (size_t)gc * 128 * Ff,
                  dsm, tid, acc);
        __syncthreads();   /* smem reuse across gc iterations */

        const int c0 = gc * 128 + wn * 64 + (lane & 3) * 2;
#pragma unroll
        for (int mt = 0; mt < 2; mt++)
#pragma unroll
            for (int nt = 0; nt < 8; nt++) {
                const int cc = c0 + nt * 8;
                const float bx = b2[cc], by = b2[cc + 1];
                const float wx = wout[cc], wy = wout[cc + 1];
                part[mt][0] += fmaxf(acc[mt][nt][0] + bx, 0.f) * wx
                             + fmaxf(acc[mt][nt][1] + by, 0.f) * wy;
                part[mt][1] += fmaxf(acc[mt][nt][2] + bx, 0.f) * wx
                             + fmaxf(acc[mt][nt][3] + by, 0.f) * wy;
            }
    }

#pragma unroll
    for (int mt = 0; mt < 2; mt++)
#pragma unroll
        for (int h = 0; h < 2; h++) {
            float v = part[mt][h];
            v += __shfl_xor_sync(0xffffffffu, v, 1);
            v += __shfl_xor_sync(0xffffffffu, v, 2);
            part[mt][h] = v;
        }
    if ((lane & 3) == 0) {
#pragma unroll
        for (int mt = 0; mt < 2; mt++)
#pragma unroll
            for (int h = 0; h < 2; h++)
                red[wm * 32 + mt * 16 + h * 8 + (lane >> 2)][wn] = part[mt][h];
    }
    __syncthreads();

    if (tid < 128) {
        float s = red[tid][0] + red[tid][1] + boutp[0];
        int gr = rb * 128 + tid;
        int b = gr / ppb, p = gr - b * ppb;
        int i, j;
        if (full) { i = c_pi[p]; j = c_pj[p]; } else { i = p; j = ZI; }
        adj[b * 121 + i * 11 + j] = s;
        adj[b * 121 + j * 11 + i] = s;
    }
}

/* ------------------------------------------------------------------ */
/* fused: softmax(adj[b,ZI,:]) + m_base + cur/m_z splits (+ col init at t0) */
__global__ void k_attn(const float* __restrict__ nf, const float* __restrict__ adj,
                       int colsel, int t0)
{
    __shared__ float a_sh[11];
    __shared__ float azz_s;

    const int b = blockIdx.x, ch = blockIdx.y, tid = threadIdx.x;

    if (tid < 32) {
        float v = (tid < 11) ? adj[b * 121 + ZI * 11 + tid] : -1e30f;
        float m = v;
#pragma unroll
        for (int o = 16; o > 0; o >>= 1) m = fmaxf(m, __shfl_xor_sync(0xffffffffu, m, o));
        float e = (tid < 11) ? expf(v - m) : 0.f;
        float s = e;
#pragma unroll
        for (int o = 16; o > 0; o >>= 1) s += __shfl_xor_sync(0xffffffffu, s, o);
        float a = e / s;
        if (tid < 11) a_sh[tid] = a;
        if (tid == ZI) azz_s = a;
        if (ch == 0) {
            if (tid < 11) g_az[b * 12 + tid] = a;
            if (tid == ZI) g_az[b * 12 + 11] = a;
        }
    }
    __syncthreads();

    const int f = ch * 128 + tid;
    const int idx = b * Ff + f;
    float mb = 0.f;
#pragma unroll
    for (int j = 0; j < 10; j++)
        mb += a_sh[j] * nf[(size_t)(b * Nn + j) * Ff + f];
    g_mb[idx] = mb;

    float cur = t0 ? nf[(size_t)(b * Nn + ZI) * Ff + f] : colptr(colsel)[idx];
    if (t0) colptr(colsel)[idx] = cur;
    float mz = mb + azz_s * cur;
    split1(cur, g_czh[idx], g_czl[idx]);
    split1(mz,  g_mzh[idx], g_mzl[idx]);
}

/* ------------------------------------------------------------------ */
/* K5: gi = m_z @ W_ih^T (z=0) ; gh = cur @ W_hh^T (z=1) */
__global__ __launch_bounds__(256, 2)
void k_gru(void)
{
    extern __shared__ char dsm[];
    const int tid = threadIdx.x, lane = tid & 31, wid = tid >> 5;
    const int wm = wid & 3, wn = wid >> 2;
    const int rb = blockIdx.x, cb = blockIdx.y, wh = blockIdx.z;

    const unsigned short* Ah = (wh ? g_czh : g_mzh) + (size_t)rb * 128 * Ff;
    const unsigned short* Al = (wh ? g_czl : g_mzl) + (size_t)rb * 128 * Ff;
    const unsigned short* Bh = (wh ? g_Whhh : g_Wihh) + (size_t)cb * 128 * Ff;
    const unsigned short* Bl = (wh ? g_Whhl : g_Wihl) + (size_t)cb * 128 * Ff;
    float* out = wh ? g_gh : g_gi;

    float acc[2][8][4];
#pragma unroll
    for (int a = 0; a < 2; a++)
#pragma unroll
        for (int b = 0; b < 8; b++)
#pragma unroll
            for (int c = 0; c < 4; c++) acc[a][b][c] = 0.f;

    gemm_pipe(Ah, Al, Bh, Bl, dsm, tid, acc);

    const int r0 = rb * 128 + wm * 32 + (lane >> 2);
    const int c0 = cb * 128 + wn * 64 + (lane & 3) * 2;
#pragma unroll
    for (int mt = 0; mt < 2; mt++)
#pragma unroll
        for (int nt = 0; nt < 8; nt++) {
            const int cc = c0 + nt * 8;
            const int rr = r0 + mt * 16;
            *(float2*)(out + (size_t)rr * G3 + cc)       = make_float2(acc[mt][nt][0], acc[mt][nt][1]);
            *(float2*)(out + (size_t)(rr + 8) * G3 + cc) = make_float2(acc[mt][nt][2], acc[mt][nt][3]);
        }
}

/* ------------------------------------------------------------------ */
/* GRU gates; produce next-step splits, or write final output directly */
__global__ void k_gate(int colsel, float* __restrict__ dst, int final_step)
{
    int idx = blockIdx.x * 256 + threadIdx.x;
    int b = idx >> 9, f = idx & 511;
    const float* cur = colptr(colsel);
    float* nxt = colptr(1 - colsel);
    const float* gib = g_gi + b * G3;
    const float* ghb = g_gh + b * G3;
    float ir = gib[f],         hr = ghb[f];
    float iz = gib[512 + f],   hz = ghb[512 + f];
    float in_ = gib[1024 + f], hn = ghb[1024 + f];
    float rr = 1.f / (1.f + expf(-(ir + hr)));
    float zz = 1.f / (1.f + expf(-(iz + hz)));
    float nn = tanhf(in_ + rr * hn);
    float h = cur[idx];
    float v = (1.f - zz) * nn + zz * h;
    nxt[idx] = v;
    if (final_step) {
        dst[idx] = v;
    } else {
        float az = g_az[b * 12 + 11];
        float mz = g_mb[idx] + az * v;
        split1(v,  g_czh[idx], g_czl[idx]);
        split1(mz, g_mzh[idx], g_mzl[idx]);
    }
}

/* ------------------------------------------------------------------ */
extern "C" void kernel_launch(void* const* d_in, const int* in_sizes, int n_in,
                              void* d_out, int out_size)
{
    const float* nf  = (const float*)d_in[0];
    const float* W1  = (const float*)d_in[1];
    const float* b1  = (const float*)d_in[2];
    const float* W2  = (const float*)d_in[3];
    const float* b2  = (const float*)d_in[4];
    const float* wo  = (const float*)d_in[5];
    const float* bo  = (const float*)d_in[6];
    const float* Wih = (const float*)d_in[7];
    const float* Whh = (const float*)d_in[8];

    float* adj    = (float*)d_out;
    float* colout = (float*)d_out + Bb * 121;

    cudaFuncSetAttribute(k_mlp1, cudaFuncAttributeMaxDynamicSharedMemorySize, DSMEM);
    cudaFuncSetAttribute(k_mlp2, cudaFuncAttributeMaxDynamicSharedMemorySize, DSMEM);
    cudaFuncSetAttribute(k_gru,  cudaFuncAttributeMaxDynamicSharedMemorySize, DSMEM);

    k_split_all<<<(2 * W1_E + 2 * WIH_E) / 1024, 256>>>(W1, W2, Wih, Whh);

    int sel = 0;
    for (int t = 0; t < 3; t++) {
        const int rows = (t == 0) ? R0 : R1;
        const int ppb  = (t == 0) ? PPF : Nn;
        const int full = (t == 0) ? 1 : 0;
        const int t0   = (t == 0) ? 1 : 0;
        k_egen<<<(rows * (Ff / 4)) / 256, 256>>>(nf, sel, ppb, full, t0);
        k_mlp1<<<dim3(rows / 128, 4), 256, DSMEM>>>(b1);
        k_mlp2<<<rows / 128, 256, DSMEM>>>(b2, wo, bo, adj, ppb, full);
        k_attn<<<dim3(Bb, 4), 128>>>(nf, adj, sel, t0);
        for (int s = 0; s < 3; s++) {
            const int fin = (t == 2 && s == 2) ? 1 : 0;
            k_gru<<<dim3(Bb / 128, G3 / 128, 2), 256, DSMEM>>>();
            k_gate<<<(Bb * Ff) / 256, 256>>>(sel, colout, fin);
            sel = 1 - sel;
        }
    }
}

// round 16
// speedup vs baseline: 1.4684x; 1.2914x over previous
#include <cuda_runtime.h>
#include <cuda_bf16.h>
#include <cuda_fp16.h>
#include <math.h>
#include <stdint.h>

#define Bb 1024
#define Nn 11
#define Ff 512
#define ZI 10
#define PPF 66
#define R0 (Bb*PPF)
#define R1 (Bb*Nn)
#define G3 1536

#define KC 32
#define NCHUNK (Ff/KC)          /* 16 */
#define SSTR 40                 /* 16-bit elems per smem row (32 data + 8 pad) */
#define PL 10240                /* bytes per plane: 128*40*2 */
#define ST4 (4*PL)              /* bf16 path stage (A_hi,A_lo,B_hi,B_lo) = 40KB */
#define ST3 (3*PL)              /* fp16 path stage (A,B_hi,B_lo) = 30KB */
#define DSMEM (2*ST4)           /* 81920 (max of both paths) */

/* ------------------------------------------------------------------ */
__device__ __forceinline__ uint32_t smaddr(const void* p) {
    uint32_t a;
    asm("{ .reg .u64 t; cvta.to.shared.u64 t, %1; cvt.u32.u64 %0, t; }"
        : "=r"(a) : "l"(p));
    return a;
}
__device__ __forceinline__ void ldm4(uint32_t a, uint32_t* r) {
    asm volatile("ldmatrix.sync.aligned.m8n8.x4.shared.b16 {%0,%1,%2,%3}, [%4];"
                 : "=r"(r[0]), "=r"(r[1]), "=r"(r[2]), "=r"(r[3]) : "r"(a));
}
/* bf16 mma */
__device__ __forceinline__ void mma_bf(float* d, const uint32_t* a, uint32_t b0, uint32_t b1) {
    asm volatile(
        "mma.sync.aligned.m16n8k16.row.col.f32.bf16.bf16.f32 "
        "{%0,%1,%2,%3},{%4,%5,%6,%7},{%8,%9},{%0,%1,%2,%3};"
        : "+f"(d[0]), "+f"(d[1]), "+f"(d[2]), "+f"(d[3])
        : "r"(a[0]), "r"(a[1]), "r"(a[2]), "r"(a[3]), "r"(b0), "r"(b1));
}
/* fp16 mma */
__device__ __forceinline__ void mma_hf(float* d, const uint32_t* a, uint32_t b0, uint32_t b1) {
    asm volatile(
        "mma.sync.aligned.m16n8k16.row.col.f32.f16.f16.f32 "
        "{%0,%1,%2,%3},{%4,%5,%6,%7},{%8,%9},{%0,%1,%2,%3};"
        : "+f"(d[0]), "+f"(d[1]), "+f"(d[2]), "+f"(d[3])
        : "r"(a[0]), "r"(a[1]), "r"(a[2]), "r"(a[3]), "r"(b0), "r"(b1));
}
__device__ __forceinline__ void split1(float v, unsigned short& h, unsigned short& l) {
    __nv_bfloat16 bh = __float2bfloat16_rn(v);
    float r = v - __bfloat162float(bh);
    __nv_bfloat16 bl = __float2bfloat16_rn(r);
    h = *(unsigned short*)&bh;
    l = *(unsigned short*)&bl;
}
__device__ __forceinline__ void split1h(float v, unsigned short& h, unsigned short& l) {
    __half hh = __float2half_rn(v);
    float r = v - __half2float(hh);
    __half hl = __float2half_rn(r);
    h = *(unsigned short*)&hh;
    l = *(unsigned short*)&hl;
}

/* ------------------------------------------------------------------ */
__constant__ int c_pi[66] = {
  0,0,0,0,0,0,0,0,0,0,0, 1,1,1,1,1,1,1,1,1,1, 2,2,2,2,2,2,2,2,2,
  3,3,3,3,3,3,3,3, 4,4,4,4,4,4,4, 5,5,5,5,5,5, 6,6,6,6,6, 7,7,7,7, 8,8,8, 9,9, 10};
__constant__ int c_pj[66] = {
  0,1,2,3,4,5,6,7,8,9,10, 1,2,3,4,5,6,7,8,9,10, 2,3,4,5,6,7,8,9,10,
  3,4,5,6,7,8,9,10, 4,5,6,7,8,9,10, 5,6,7,8,9,10, 6,7,8,9,10, 7,8,9,10, 8,9,10, 9,10, 10};

/* f32 scratch */
__device__ float g_colA[Bb * Ff];
__device__ float g_colB[Bb * Ff];
__device__ float g_az[Bb * 12];
__device__ float g_mb[Bb * Ff];
__device__ float g_gi[Bb * G3];
__device__ float g_gh[Bb * G3];

/* fp16 planes for MLP path */
__device__ unsigned short g_W1h[Ff * Ff],  g_W1l[Ff * Ff];      /* fp16 hi/lo */
__device__ unsigned short g_W2h[Ff * Ff],  g_W2l[Ff * Ff];      /* fp16 hi/lo */
__device__ unsigned short g_Ea[R0 * Ff];                        /* fp16 single */
__device__ unsigned short g_H1a[R0 * Ff];                       /* fp16 single */
/* bf16 planes for GRU path */
__device__ unsigned short g_Wihh[G3 * Ff], g_Wihl[G3 * Ff];
__device__ unsigned short g_Whhh[G3 * Ff], g_Whhl[G3 * Ff];
__device__ unsigned short g_czh[Bb * Ff],  g_czl[Bb * Ff];
__device__ unsigned short g_mzh[Bb * Ff],  g_mzl[Bb * Ff];

__device__ __forceinline__ float* colptr(int sel) { return sel ? g_colB : g_colA; }

/* ------------------------------------------------------------------ */
/* fp16 2-term chunk: planes A@0, Bh@PL, Bl@2PL. Term-major order. */
__device__ __forceinline__ void chunk_hf(uint32_t base, int wm, int wn,
                                         int lane, float acc[2][8][4])
{
    const int rsel = lane & 15;
    const int ksel = (lane >> 4) * 8;
#pragma unroll
    for (int s = 0; s < 2; s++) {
        uint32_t aa[2][4];
#pragma unroll
        for (int mt = 0; mt < 2; mt++) {
            uint32_t off = (uint32_t)((wm*32 + mt*16 + rsel) * SSTR + s*16 + ksel) * 2;
            ldm4(base + 0*PL + off, aa[mt]);
        }
#pragma unroll
        for (int np = 0; np < 4; np++) {
            uint32_t bh[4], bl[4];
            uint32_t off = (uint32_t)((wn*64 + np*16 + rsel) * SSTR + s*16 + ksel) * 2;
            ldm4(base + 1*PL + off, bh);
            ldm4(base + 2*PL + off, bl);
#pragma unroll
            for (int mt = 0; mt < 2; mt++)
#pragma unroll
                for (int h = 0; h < 2; h++)
                    mma_hf(acc[mt][np*2 + h], aa[mt], bh[h], bh[h+2]);
#pragma unroll
            for (int mt = 0; mt < 2; mt++)
#pragma unroll
                for (int h = 0; h < 2; h++)
                    mma_hf(acc[mt][np*2 + h], aa[mt], bl[h], bl[h+2]);
        }
    }
}

/* bf16 3-term chunk (GRU path), term-major */
__device__ __forceinline__ void chunk_bf(uint32_t base, int wm, int wn,
                                         int lane, float acc[2][8][4])
{
    const int rsel = lane & 15;
    const int ksel = (lane >> 4) * 8;
#pragma unroll
    for (int s = 0; s < 2; s++) {
        uint32_t ah[2][4], al[2][4];
#pragma unroll
        for (int mt = 0; mt < 2; mt++) {
            uint32_t off = (uint32_t)((wm*32 + mt*16 + rsel) * SSTR + s*16 + ksel) * 2;
            ldm4(base + 0*PL + off, ah[mt]);
            ldm4(base + 1*PL + off, al[mt]);
        }
#pragma unroll
        for (int np = 0; np < 4; np++) {
            uint32_t bh[4], bl[4];
            uint32_t off = (uint32_t)((wn*64 + np*16 + rsel) * SSTR + s*16 + ksel) * 2;
            ldm4(base + 2*PL + off, bh);
            ldm4(base + 3*PL + off, bl);
#pragma unroll
            for (int mt = 0; mt < 2; mt++)
#pragma unroll
                for (int h = 0; h < 2; h++)
                    mma_bf(acc[mt][np*2 + h], ah[mt], bh[h], bh[h+2]);
#pragma unroll
            for (int mt = 0; mt < 2; mt++)
#pragma unroll
                for (int h = 0; h < 2; h++)
                    mma_bf(acc[mt][np*2 + h], ah[mt], bl[h], bl[h+2]);
#pragma unroll
            for (int mt = 0; mt < 2; mt++)
#pragma unroll
                for (int h = 0; h < 2; h++)
                    mma_bf(acc[mt][np*2 + h], al[mt], bh[h], bh[h+2]);
        }
    }
}

/* fp16 pipeline: 3 planes (A, Bh, Bl), double-buffered */
__device__ __forceinline__ void pipe_hf(
    const unsigned short* __restrict__ Aa,
    const unsigned short* __restrict__ Bh, const unsigned short* __restrict__ Bl,
    char* dsm, int tid, float acc[2][8][4])
{
    const uint32_t sb = smaddr(dsm);
    const int lane = tid & 31, wid = tid >> 5;
    const int wm = wid & 3, wn = wid >> 2;

    const int q8 = (tid & 3) * 8;
    const int r0 = tid >> 2;
    const unsigned short* pg[3] = { Aa, Bh, Bl };
    const int go0 = r0 * Ff + q8;
    const int go1 = (r0 + 64) * Ff + q8;
    const uint32_t so0 = (uint32_t)(r0 * SSTR + q8) * 2;
    const uint32_t so1 = (uint32_t)((r0 + 64) * SSTR + q8) * 2;

    auto stg = [&](int c, int s) {
        uint32_t db = sb + (uint32_t)s * ST3;
        const int ke = c * KC;
#pragma unroll
        for (int pl = 0; pl < 3; pl++) {
            asm volatile("cp.async.ca.shared.global [%0],[%1],16;"
                         :: "r"(db + (uint32_t)pl * PL + so0), "l"(pg[pl] + go0 + ke) : "memory");
            asm volatile("cp.async.ca.shared.global [%0],[%1],16;"
                         :: "r"(db + (uint32_t)pl * PL + so1), "l"(pg[pl] + go1 + ke) : "memory");
        }
        asm volatile("cp.async.commit_group;" ::: "memory");
    };

    stg(0, 0);
    asm volatile("cp.async.wait_group 0;" ::: "memory");
    __syncthreads();
    for (int c = 0; c < NCHUNK; c++) {
        if (c + 1 < NCHUNK) stg(c + 1, (c + 1) & 1);
        chunk_hf(sb + (uint32_t)(c & 1) * ST3, wm, wn, lane, acc);
        if (c + 1 < NCHUNK) asm volatile("cp.async.wait_group 0;" ::: "memory");
        __syncthreads();
    }
}

/* bf16 pipeline: 4 planes, double-buffered (GRU) */
__device__ __forceinline__ void pipe_bf(
    const unsigned short* __restrict__ Ah, const unsigned short* __restrict__ Al,
    const unsigned short* __restrict__ Bh, const unsigned short* __restrict__ Bl,
    char* dsm, int tid, float acc[2][8][4])
{
    const uint32_t sb = smaddr(dsm);
    const int lane = tid & 31, wid = tid >> 5;
    const int wm = wid & 3, wn = wid >> 2;

    const int q8 = (tid & 3) * 8;
    const int r0 = tid >> 2;
    const unsigned short* pg[4] = { Ah, Al, Bh, Bl };
    const int go0 = r0 * Ff + q8;
    const int go1 = (r0 + 64) * Ff + q8;
    const uint32_t so0 = (uint32_t)(r0 * SSTR + q8) * 2;
    const uint32_t so1 = (uint32_t)((r0 + 64) * SSTR + q8) * 2;

    auto stg = [&](int c, int s) {
        uint32_t db = sb + (uint32_t)s * ST4;
        const int ke = c * KC;
#pragma unroll
        for (int pl = 0; pl < 4; pl++) {
            asm volatile("cp.async.ca.shared.global [%0],[%1],16;"
                         :: "r"(db + (uint32_t)pl * PL + so0), "l"(pg[pl] + go0 + ke) : "memory");
            asm volatile("cp.async.ca.shared.global [%0],[%1],16;"
                         :: "r"(db + (uint32_t)pl * PL + so1), "l"(pg[pl] + go1 + ke) : "memory");
        }
        asm volatile("cp.async.commit_group;" ::: "memory");
    };

    stg(0, 0);
    asm volatile("cp.async.wait_group 0;" ::: "memory");
    __syncthreads();
    for (int c = 0; c < NCHUNK; c++) {
        if (c + 1 < NCHUNK) stg(c + 1, (c + 1) & 1);
        chunk_bf(sb + (uint32_t)(c & 1) * ST4, wm, wn, lane, acc);
        if (c + 1 < NCHUNK) asm volatile("cp.async.wait_group 0;" ::: "memory");
        __syncthreads();
    }
}

/* ------------------------------------------------------------------ */
#define W1_E (Ff*Ff)
#define WIH_E (G3*Ff)
/* W1,W2 -> fp16 hi/lo; Wih,Whh -> bf16 hi/lo */
__global__ void k_split_all(const float* __restrict__ W1, const float* __restrict__ W2,
                            const float* __restrict__ Wih, const float* __restrict__ Whh)
{
    int i4 = (blockIdx.x * 256 + threadIdx.x) * 4;
    const float* src;
    unsigned short *dh, *dl;
    int o, ishalf;
    if (i4 < W1_E)               { src = W1;  dh = g_W1h;  dl = g_W1l;  o = i4;                ishalf = 1; }
    else if (i4 < 2*W1_E)        { src = W2;  dh = g_W2h;  dl = g_W2l;  o = i4 - W1_E;         ishalf = 1; }
    else if (i4 < 2*W1_E+WIH_E)  { src = Wih; dh = g_Wihh; dl = g_Wihl; o = i4 - 2*W1_E;       ishalf = 0; }
    else                         { src = Whh; dh = g_Whhh; dl = g_Whhl; o = i4 - 2*W1_E - WIH_E; ishalf = 0; }
    float4 v = *(const float4*)(src + o);
    ushort4 h, l;
    if (ishalf) {
        split1h(v.x, h.x, l.x); split1h(v.y, h.y, l.y);
        split1h(v.z, h.z, l.z); split1h(v.w, h.w, l.w);
    } else {
        split1(v.x, h.x, l.x); split1(v.y, h.y, l.y);
        split1(v.z, h.z, l.z); split1(v.w, h.w, l.w);
    }
    *(ushort4*)(dh + o) = h;
    *(ushort4*)(dl + o) = l;
}

/* E rows: E[r][f] = x_i[f]*x_j[f], fp16 single plane */
__global__ void k_egen(const float* __restrict__ nf, int colsel, int ppb, int full, int t0)
{
    int t4 = blockIdx.x * 256 + threadIdx.x;
    int r = t4 >> 7, q = t4 & 127;
    int b = r / ppb, p = r - b * ppb;
    int i, j;
    if (full) { i = c_pi[p]; j = c_pj[p]; } else { i = p; j = ZI; }
    const float* colb = t0 ? (nf + (size_t)(b * Nn + ZI) * Ff)
                           : (colptr(colsel) + (size_t)b * Ff);
    const float* xi = (i == ZI) ? colb : (nf + (size_t)(b * Nn + i) * Ff);
    const float* xj = (j == ZI) ? colb : (nf + (size_t)(b * Nn + j) * Ff);
    float4 a = *(const float4*)(xi + q * 4);
    float4 c2 = *(const float4*)(xj + q * 4);
    __half h0 = __float2half_rn(a.x * c2.x);
    __half h1 = __float2half_rn(a.y * c2.y);
    __half h2 = __float2half_rn(a.z * c2.z);
    __half h3 = __float2half_rn(a.w * c2.w);
    ushort4 h;
    h.x = *(unsigned short*)&h0; h.y = *(unsigned short*)&h1;
    h.z = *(unsigned short*)&h2; h.w = *(unsigned short*)&h3;
    *(ushort4*)(g_Ea + (size_t)r * Ff + q * 4) = h;
}

/* ------------------------------------------------------------------ */
/* K1: H1 = relu(E @ W1^T + b1), fp16 path, output fp16 single */
__global__ __launch_bounds__(256, 2)
void k_mlp1(const float* __restrict__ b1)
{
    extern __shared__ char dsm[];
    const int tid = threadIdx.x, lane = tid & 31, wid = tid >> 5;
    const int wm = wid & 3, wn = wid >> 2;
    const int rb = blockIdx.x, cb = blockIdx.y;

    float acc[2][8][4];
#pragma unroll
    for (int a = 0; a < 2; a++)
#pragma unroll
        for (int b = 0; b < 8; b++)
#pragma unroll
            for (int c = 0; c < 4; c++) acc[a][b][c] = 0.f;

    pipe_hf(g_Ea + (size_t)rb * 128 * Ff,
            g_W1h + (size_t)cb * 128 * Ff, g_W1l + (size_t)cb * 128 * Ff,
            dsm, tid, acc);

    const int r0 = rb * 128 + wm * 32 + (lane >> 2);
    const int c0 = cb * 128 + wn * 64 + (lane & 3) * 2;
#pragma unroll
    for (int mt = 0; mt < 2; mt++)
#pragma unroll
        for (int nt = 0; nt < 8; nt++) {
            const int cc = c0 + nt * 8;
            const float bx = b1[cc], by = b1[cc + 1];
#pragma unroll
            for (int hh = 0; hh < 2; hh++) {
                const int rr = r0 + mt * 16 + hh * 8;
                float v0 = fmaxf(acc[mt][nt][hh*2+0] + bx, 0.f);
                float v1 = fmaxf(acc[mt][nt][hh*2+1] + by, 0.f);
                __half q0 = __float2half_rn(v0);
                __half q1 = __float2half_rn(v1);
                ushort2 h;
                h.x = *(unsigned short*)&q0;
                h.y = *(unsigned short*)&q1;
                *(ushort2*)(g_H1a + (size_t)rr * Ff + cc) = h;
            }
        }
}

/* ------------------------------------------------------------------ */
/* K2: adj = sum_g wout[g]*relu((H1 @ W2^T)+b2) + bout, fp16 path */
__global__ __launch_bounds__(256, 2)
void k_mlp2(const float* __restrict__ b2, const float* __restrict__ wout,
            const float* __restrict__ boutp, float* __restrict__ adj,
            int ppb, int full)
{
    extern __shared__ char dsm[];
    __shared__ float red[128][2];

    const int tid = threadIdx.x, lane = tid & 31, wid = tid >> 5;
    const int wm = wid & 3, wn = wid >> 2;
    const int rb = blockIdx.x;

    float part[2][2] = {{0.f, 0.f}, {0.f, 0.f}};

    for (int gc = 0; gc < 4; gc++) {
        float acc[2][8][4];
#pragma unroll
        for (int a = 0; a < 2; a++)
#pragma unroll
            for (int b = 0; b < 8; b++)
#pragma unroll
                for (int c = 0; c < 4; c++) acc[a][b][c] = 0.f;

        pipe_hf(g_H1a + (size_t)rb * 128 * Ff,
                g_W2h + (size_t)gc * 128 * Ff, g_W2l + (size_t)gc * 128 * Ff,
                dsm, tid, acc);
        __syncthreads();   /* smem reuse across gc iterations */

        const int c0 = gc * 128 + wn * 64 + (lane & 3) * 2;
#pragma unroll
        for (int mt = 0; mt < 2; mt++)
#pragma unroll
            for (int nt = 0; nt < 8; nt++) {
                const int cc = c0 + nt * 8;
                const float bx = b2[cc], by = b2[cc + 1];
                const float wx = wout[cc], wy = wout[cc + 1];
                part[mt][0] += fmaxf(acc[mt][nt][0] + bx, 0.f) * wx
                             + fmaxf(acc[mt][nt][1] + by, 0.f) * wy;
                part[mt][1] += fmaxf(acc[mt][nt][2] + bx, 0.f) * wx
                             + fmaxf(acc[mt][nt][3] + by, 0.f) * wy;
            }
    }

#pragma unroll
    for (int mt = 0; mt < 2; mt++)
#pragma unroll
        for (int h = 0; h < 2; h++) {
            float v = part[mt][h];
            v += __shfl_xor_sync(0xffffffffu, v, 1);
            v += __shfl_xor_sync(0xffffffffu, v, 2);
            part[mt][h] = v;
        }
    if ((lane & 3) == 0) {
#pragma unroll
        for (int mt = 0; mt < 2; mt++)
#pragma unroll
            for (int h = 0; h < 2; h++)
                red[wm * 32 + mt * 16 + h * 8 + (lane >> 2)][wn] = part[mt][h];
    }
    __syncthreads();

    if (tid < 128) {
        float s = red[tid][0] + red[tid][1] + boutp[0];
        int gr = rb * 128 + tid;
        int b = gr / ppb, p = gr - b * ppb;
        int i, j;
        if (full) { i = c_pi[p]; j = c_pj[p]; } else { i = p; j = ZI; }
        adj[b * 121 + i * 11 + j] = s;
        adj[b * 121 + j * 11 + i] = s;
    }
}

/* ------------------------------------------------------------------ */
/* fused: softmax(adj[b,ZI,:]) + m_base + cur/m_z splits (+ col init at t0) */
__global__ void k_attn(const float* __restrict__ nf, const float* __restrict__ adj,
                       int colsel, int t0)
{
    __shared__ float a_sh[11];
    __shared__ float azz_s;

    const int b = blockIdx.x, ch = blockIdx.y, tid = threadIdx.x;

    if (tid < 32) {
        float v = (tid < 11) ? adj[b * 121 + ZI * 11 + tid] : -1e30f;
        float m = v;
#pragma unroll
        for (int o = 16; o > 0; o >>= 1) m = fmaxf(m, __shfl_xor_sync(0xffffffffu, m, o));
        float e = (tid < 11) ? expf(v - m) : 0.f;
        float s = e;
#pragma unroll
        for (int o = 16; o > 0; o >>= 1) s += __shfl_xor_sync(0xffffffffu, s, o);
        float a = e / s;
        if (tid < 11) a_sh[tid] = a;
        if (tid == ZI) azz_s = a;
        if (ch == 0) {
            if (tid < 11) g_az[b * 12 + tid] = a;
            if (tid == ZI) g_az[b * 12 + 11] = a;
        }
    }
    __syncthreads();

    const int f = ch * 128 + tid;
    const int idx = b * Ff + f;
    float mb = 0.f;
#pragma unroll
    for (int j = 0; j < 10; j++)
        mb += a_sh[j] * nf[(size_t)(b * Nn + j) * Ff + f];
    g_mb[idx] = mb;

    float cur = t0 ? nf[(size_t)(b * Nn + ZI) * Ff + f] : colptr(colsel)[idx];
    if (t0) colptr(colsel)[idx] = cur;
    float mz = mb + azz_s * cur;
    split1(cur, g_czh[idx], g_czl[idx]);
    split1(mz,  g_mzh[idx], g_mzl[idx]);
}

/* ------------------------------------------------------------------ */
/* K5: gi = m_z @ W_ih^T (z=0) ; gh = cur @ W_hh^T (z=1) — bf16 3-term */
__global__ __launch_bounds__(256, 2)
void k_gru(void)
{
    extern __shared__ char dsm[];
    const int tid = threadIdx.x, lane = tid & 31, wid = tid >> 5;
    const int wm = wid & 3, wn = wid >> 2;
    const int rb = blockIdx.x, cb = blockIdx.y, wh = blockIdx.z;

    const unsigned short* Ah = (wh ? g_czh : g_mzh) + (size_t)rb * 128 * Ff;
    const unsigned short* Al = (wh ? g_czl : g_mzl) + (size_t)rb * 128 * Ff;
    const unsigned short* Bh = (wh ? g_Whhh : g_Wihh) + (size_t)cb * 128 * Ff;
    const unsigned short* Bl = (wh ? g_Whhl : g_Wihl) + (size_t)cb * 128 * Ff;
    float* out = wh ? g_gh : g_gi;

    float acc[2][8][4];
#pragma unroll
    for (int a = 0; a < 2; a++)
#pragma unroll
        for (int b = 0; b < 8; b++)
#pragma unroll
            for (int c = 0; c < 4; c++) acc[a][b][c] = 0.f;

    pipe_bf(Ah, Al, Bh, Bl, dsm, tid, acc);

    const int r0 = rb * 128 + wm * 32 + (lane >> 2);
    const int c0 = cb * 128 + wn * 64 + (lane & 3) * 2;
#pragma unroll
    for (int mt = 0; mt < 2; mt++)
#pragma unroll
        for (int nt = 0; nt < 8; nt++) {
            const int cc = c0 + nt * 8;
            const int rr = r0 + mt * 16;
            *(float2*)(out + (size_t)rr * G3 + cc)       = make_float2(acc[mt][nt][0], acc[mt][nt][1]);
            *(float2*)(out + (size_t)(rr + 8) * G3 + cc) = make_float2(acc[mt][nt][2], acc[mt][nt][3]);
        }
}

/* ------------------------------------------------------------------ */
/* GRU gates; produce next-step splits, or write final output directly */
__global__ void k_gate(int colsel, float* __restrict__ dst, int final_step)
{
    int idx = blockIdx.x * 256 + threadIdx.x;
    int b = idx >> 9, f = idx & 511;
    const float* cur = colptr(colsel);
    float* nxt = colptr(1 - colsel);
    const float* gib = g_gi + b * G3;
    const float* ghb = g_gh + b * G3;
    float ir = gib[f],         hr = ghb[f];
    float iz = gib[512 + f],   hz = ghb[512 + f];
    float in_ = gib[1024 + f], hn = ghb[1024 + f];
    float rr = 1.f / (1.f + expf(-(ir + hr)));
    float zz = 1.f / (1.f + expf(-(iz + hz)));
    float nn = tanhf(in_ + rr * hn);
    float h = cur[idx];
    float v = (1.f - zz) * nn + zz * h;
    nxt[idx] = v;
    if (final_step) {
        dst[idx] = v;
    } else {
        float az = g_az[b * 12 + 11];
        float mz = g_mb[idx] + az * v;
        split1(v,  g_czh[idx], g_czl[idx]);
        split1(mz, g_mzh[idx], g_mzl[idx]);
    }
}

/* ------------------------------------------------------------------ */
extern "C" void kernel_launch(void* const* d_in, const int* in_sizes, int n_in,
                              void* d_out, int out_size)
{
    const float* nf  = (const float*)d_in[0];
    const float* W1  = (const float*)d_in[1];
    const float* b1  = (const float*)d_in[2];
    const float* W2  = (const float*)d_in[3];
    const float* b2  = (const float*)d_in[4];
    const float* wo  = (const float*)d_in[5];
    const float* bo  = (const float*)d_in[6];
    const float* Wih = (const float*)d_in[7];
    const float* Whh = (const float*)d_in[8];

    float* adj    = (float*)d_out;
    float* colout = (float*)d_out + Bb * 121;

    cudaFuncSetAttribute(k_mlp1, cudaFuncAttributeMaxDynamicSharedMemorySize, DSMEM);
    cudaFuncSetAttribute(k_mlp2, cudaFuncAttributeMaxDynamicSharedMemorySize, DSMEM);
    cudaFuncSetAttribute(k_gru,  cudaFuncAttributeMaxDynamicSharedMemorySize, DSMEM);

    k_split_all<<<(2 * W1_E + 2 * WIH_E) / 1024, 256>>>(W1, W2, Wih, Whh);

    int sel = 0;
    for (int t = 0; t < 3; t++) {
        const int rows = (t == 0) ? R0 : R1;
        const int ppb  = (t == 0) ? PPF : Nn;
        const int full = (t == 0) ? 1 : 0;
        const int t0   = (t == 0) ? 1 : 0;
        k_egen<<<(rows * (Ff / 4)) / 256, 256>>>(nf, sel, ppb, full, t0);
        k_mlp1<<<dim3(rows / 128, 4), 256, DSMEM>>>(b1);
        k_mlp2<<<rows / 128, 256, DSMEM>>>(b2, wo, bo, adj, ppb, full);
        k_attn<<<dim3(Bb, 4), 128>>>(nf, adj, sel, t0);
        for (int s = 0; s < 3; s++) {
            const int fin = (t == 2 && s == 2) ? 1 : 0;
            k_gru<<<dim3(Bb / 128, G3 / 128, 2), 256, DSMEM>>>();
            k_gate<<<(Bb * Ff) / 256, 256>>>(sel, colout, fin);
            sel = 1 - sel;
        }
    }
}

// round 17
// speedup vs baseline: 1.8811x; 1.2810x over previous
#include <cuda_runtime.h>
#include <cuda_bf16.h>
#include <cuda_fp16.h>
#include <math.h>
#include <stdint.h>

#define Bb 1024
#define Nn 11
#define Ff 512
#define ZI 10
#define PPF 66
#define R0 (Bb*PPF)
#define R1 (Bb*Nn)
#define G3 1536

#define KC 32
#define NCHUNK (Ff/KC)          /* 16 */
#define SSTR 40                 /* 16-bit elems per smem row (32 data + 8 pad) */
#define PL 10240                /* bytes per plane: 128*40*2 */
#define ST4 (4*PL)              /* bf16 GRU stage (A_hi,A_lo,B_hi,B_lo) = 40KB */
#define ST2 (2*PL)              /* fp16 MLP stage (A,B) = 20KB */
#define DSMEM_G (2*ST4)         /* 81920 for GRU */
#define DSMEM_M (2*ST2)         /* 40960 for MLP */

/* ------------------------------------------------------------------ */
__device__ __forceinline__ uint32_t smaddr(const void* p) {
    uint32_t a;
    asm("{ .reg .u64 t; cvta.to.shared.u64 t, %1; cvt.u32.u64 %0, t; }"
        : "=r"(a) : "l"(p));
    return a;
}
__device__ __forceinline__ void ldm4(uint32_t a, uint32_t* r) {
    asm volatile("ldmatrix.sync.aligned.m8n8.x4.shared.b16 {%0,%1,%2,%3}, [%4];"
                 : "=r"(r[0]), "=r"(r[1]), "=r"(r[2]), "=r"(r[3]) : "r"(a));
}
__device__ __forceinline__ void mma_bf(float* d, const uint32_t* a, uint32_t b0, uint32_t b1) {
    asm volatile(
        "mma.sync.aligned.m16n8k16.row.col.f32.bf16.bf16.f32 "
        "{%0,%1,%2,%3},{%4,%5,%6,%7},{%8,%9},{%0,%1,%2,%3};"
        : "+f"(d[0]), "+f"(d[1]), "+f"(d[2]), "+f"(d[3])
        : "r"(a[0]), "r"(a[1]), "r"(a[2]), "r"(a[3]), "r"(b0), "r"(b1));
}
__device__ __forceinline__ void mma_hf(float* d, const uint32_t* a, uint32_t b0, uint32_t b1) {
    asm volatile(
        "mma.sync.aligned.m16n8k16.row.col.f32.f16.f16.f32 "
        "{%0,%1,%2,%3},{%4,%5,%6,%7},{%8,%9},{%0,%1,%2,%3};"
        : "+f"(d[0]), "+f"(d[1]), "+f"(d[2]), "+f"(d[3])
        : "r"(a[0]), "r"(a[1]), "r"(a[2]), "r"(a[3]), "r"(b0), "r"(b1));
}
__device__ __forceinline__ void split1(float v, unsigned short& h, unsigned short& l) {
    __nv_bfloat16 bh = __float2bfloat16_rn(v);
    float r = v - __bfloat162float(bh);
    __nv_bfloat16 bl = __float2bfloat16_rn(r);
    h = *(unsigned short*)&bh;
    l = *(unsigned short*)&bl;
}
__device__ __forceinline__ unsigned short h1(float v) {
    __half hh = __float2half_rn(v);
    return *(unsigned short*)&hh;
}

/* ------------------------------------------------------------------ */
__constant__ int c_pi[66] = {
  0,0,0,0,0,0,0,0,0,0,0, 1,1,1,1,1,1,1,1,1,1, 2,2,2,2,2,2,2,2,2,
  3,3,3,3,3,3,3,3, 4,4,4,4,4,4,4, 5,5,5,5,5,5, 6,6,6,6,6, 7,7,7,7, 8,8,8, 9,9, 10};
__constant__ int c_pj[66] = {
  0,1,2,3,4,5,6,7,8,9,10, 1,2,3,4,5,6,7,8,9,10, 2,3,4,5,6,7,8,9,10,
  3,4,5,6,7,8,9,10, 4,5,6,7,8,9,10, 5,6,7,8,9,10, 6,7,8,9,10, 7,8,9,10, 8,9,10, 9,10, 10};

/* f32 scratch */
__device__ float g_colA[Bb * Ff];
__device__ float g_colB[Bb * Ff];
__device__ float g_az[Bb * 12];
__device__ float g_mb[Bb * Ff];
__device__ float g_gi[Bb * G3];
__device__ float g_gh[Bb * G3];

/* fp16 single planes for MLP path */
__device__ unsigned short g_W1a[Ff * Ff];
__device__ unsigned short g_W2a[Ff * Ff];
__device__ unsigned short g_Ea[R0 * Ff];
__device__ unsigned short g_H1a[R0 * Ff];
/* bf16 hi/lo planes for GRU path */
__device__ unsigned short g_Wihh[G3 * Ff], g_Wihl[G3 * Ff];
__device__ unsigned short g_Whhh[G3 * Ff], g_Whhl[G3 * Ff];
__device__ unsigned short g_czh[Bb * Ff],  g_czl[Bb * Ff];
__device__ unsigned short g_mzh[Bb * Ff],  g_mzl[Bb * Ff];

__device__ __forceinline__ float* colptr(int sel) { return sel ? g_colB : g_colA; }

/* ------------------------------------------------------------------ */
/* fp16 1-term chunk: planes A@0, B@PL. */
__device__ __forceinline__ void chunk_hf1(uint32_t base, int wm, int wn,
                                          int lane, float acc[2][8][4])
{
    const int rsel = lane & 15;
    const int ksel = (lane >> 4) * 8;
#pragma unroll
    for (int s = 0; s < 2; s++) {
        uint32_t aa[2][4];
#pragma unroll
        for (int mt = 0; mt < 2; mt++) {
            uint32_t off = (uint32_t)((wm*32 + mt*16 + rsel) * SSTR + s*16 + ksel) * 2;
            ldm4(base + 0*PL + off, aa[mt]);
        }
#pragma unroll
        for (int np = 0; np < 4; np++) {
            uint32_t bb[4];
            uint32_t off = (uint32_t)((wn*64 + np*16 + rsel) * SSTR + s*16 + ksel) * 2;
            ldm4(base + 1*PL + off, bb);
#pragma unroll
            for (int mt = 0; mt < 2; mt++)
#pragma unroll
                for (int h = 0; h < 2; h++)
                    mma_hf(acc[mt][np*2 + h], aa[mt], bb[h], bb[h+2]);
        }
    }
}

/* bf16 3-term chunk (GRU path), term-major */
__device__ __forceinline__ void chunk_bf(uint32_t base, int wm, int wn,
                                         int lane, float acc[2][8][4])
{
    const int rsel = lane & 15;
    const int ksel = (lane >> 4) * 8;
#pragma unroll
    for (int s = 0; s < 2; s++) {
        uint32_t ah[2][4], al[2][4];
#pragma unroll
        for (int mt = 0; mt < 2; mt++) {
            uint32_t off = (uint32_t)((wm*32 + mt*16 + rsel) * SSTR + s*16 + ksel) * 2;
            ldm4(base + 0*PL + off, ah[mt]);
            ldm4(base + 1*PL + off, al[mt]);
        }
#pragma unroll
        for (int np = 0; np < 4; np++) {
            uint32_t bh[4], bl[4];
            uint32_t off = (uint32_t)((wn*64 + np*16 + rsel) * SSTR + s*16 + ksel) * 2;
            ldm4(base + 2*PL + off, bh);
            ldm4(base + 3*PL + off, bl);
#pragma unroll
            for (int mt = 0; mt < 2; mt++)
#pragma unroll
                for (int h = 0; h < 2; h++)
                    mma_bf(acc[mt][np*2 + h], ah[mt], bh[h], bh[h+2]);
#pragma unroll
            for (int mt = 0; mt < 2; mt++)
#pragma unroll
                for (int h = 0; h < 2; h++)
                    mma_bf(acc[mt][np*2 + h], ah[mt], bl[h], bl[h+2]);
#pragma unroll
            for (int mt = 0; mt < 2; mt++)
#pragma unroll
                for (int h = 0; h < 2; h++)
                    mma_bf(acc[mt][np*2 + h], al[mt], bh[h], bh[h+2]);
        }
    }
}

/* fp16 pipeline: 2 planes (A, B), double-buffered */
__device__ __forceinline__ void pipe_hf1(
    const unsigned short* __restrict__ Aa, const unsigned short* __restrict__ Ba,
    char* dsm, int tid, float acc[2][8][4])
{
    const uint32_t sb = smaddr(dsm);
    const int lane = tid & 31, wid = tid >> 5;
    const int wm = wid & 3, wn = wid >> 2;

    const int q8 = (tid & 3) * 8;
    const int r0 = tid >> 2;
    const unsigned short* pg[2] = { Aa, Ba };
    const int go0 = r0 * Ff + q8;
    const int go1 = (r0 + 64) * Ff + q8;
    const uint32_t so0 = (uint32_t)(r0 * SSTR + q8) * 2;
    const uint32_t so1 = (uint32_t)((r0 + 64) * SSTR + q8) * 2;

    auto stg = [&](int c, int s) {
        uint32_t db = sb + (uint32_t)s * ST2;
        const int ke = c * KC;
#pragma unroll
        for (int pl = 0; pl < 2; pl++) {
            asm volatile("cp.async.ca.shared.global [%0],[%1],16;"
                         :: "r"(db + (uint32_t)pl * PL + so0), "l"(pg[pl] + go0 + ke) : "memory");
            asm volatile("cp.async.ca.shared.global [%0],[%1],16;"
                         :: "r"(db + (uint32_t)pl * PL + so1), "l"(pg[pl] + go1 + ke) : "memory");
        }
        asm volatile("cp.async.commit_group;" ::: "memory");
    };

    stg(0, 0);
    asm volatile("cp.async.wait_group 0;" ::: "memory");
    __syncthreads();
    for (int c = 0; c < NCHUNK; c++) {
        if (c + 1 < NCHUNK) stg(c + 1, (c + 1) & 1);
        chunk_hf1(sb + (uint32_t)(c & 1) * ST2, wm, wn, lane, acc);
        if (c + 1 < NCHUNK) asm volatile("cp.async.wait_group 0;" ::: "memory");
        __syncthreads();
    }
}

/* bf16 pipeline: 4 planes, double-buffered (GRU) */
__device__ __forceinline__ void pipe_bf(
    const unsigned short* __restrict__ Ah, const unsigned short* __restrict__ Al,
    const unsigned short* __restrict__ Bh, const unsigned short* __restrict__ Bl,
    char* dsm, int tid, float acc[2][8][4])
{
    const uint32_t sb = smaddr(dsm);
    const int lane = tid & 31, wid = tid >> 5;
    const int wm = wid & 3, wn = wid >> 2;

    const int q8 = (tid & 3) * 8;
    const int r0 = tid >> 2;
    const unsigned short* pg[4] = { Ah, Al, Bh, Bl };
    const int go0 = r0 * Ff + q8;
    const int go1 = (r0 + 64) * Ff + q8;
    const uint32_t so0 = (uint32_t)(r0 * SSTR + q8) * 2;
    const uint32_t so1 = (uint32_t)((r0 + 64) * SSTR + q8) * 2;

    auto stg = [&](int c, int s) {
        uint32_t db = sb + (uint32_t)s * ST4;
        const int ke = c * KC;
#pragma unroll
        for (int pl = 0; pl < 4; pl++) {
            asm volatile("cp.async.ca.shared.global [%0],[%1],16;"
                         :: "r"(db + (uint32_t)pl * PL + so0), "l"(pg[pl] + go0 + ke) : "memory");
            asm volatile("cp.async.ca.shared.global [%0],[%1],16;"
                         :: "r"(db + (uint32_t)pl * PL + so1), "l"(pg[pl] + go1 + ke) : "memory");
        }
        asm volatile("cp.async.commit_group;" ::: "memory");
    };

    stg(0, 0);
    asm volatile("cp.async.wait_group 0;" ::: "memory");
    __syncthreads();
    for (int c = 0; c < NCHUNK; c++) {
        if (c + 1 < NCHUNK) stg(c + 1, (c + 1) & 1);
        chunk_bf(sb + (uint32_t)(c & 1) * ST4, wm, wn, lane, acc);
        if (c + 1 < NCHUNK) asm volatile("cp.async.wait_group 0;" ::: "memory");
        __syncthreads();
    }
}

/* ------------------------------------------------------------------ */
#define W1_E (Ff*Ff)
#define WIH_E (G3*Ff)
/* W1,W2 -> fp16 single; Wih,Whh -> bf16 hi/lo */
__global__ void k_split_all(const float* __restrict__ W1, const float* __restrict__ W2,
                            const float* __restrict__ Wih, const float* __restrict__ Whh)
{
    int i4 = (blockIdx.x * 256 + threadIdx.x) * 4;
    float4 v;
    if (i4 < W1_E) {
        v = *(const float4*)(W1 + i4);
        ushort4 h = make_ushort4(h1(v.x), h1(v.y), h1(v.z), h1(v.w));
        *(ushort4*)(g_W1a + i4) = h;
    } else if (i4 < 2*W1_E) {
        int o = i4 - W1_E;
        v = *(const float4*)(W2 + o);
        ushort4 h = make_ushort4(h1(v.x), h1(v.y), h1(v.z), h1(v.w));
        *(ushort4*)(g_W2a + o) = h;
    } else {
        const float* src;
        unsigned short *dh, *dl;
        int o;
        if (i4 < 2*W1_E + WIH_E) { src = Wih; dh = g_Wihh; dl = g_Wihl; o = i4 - 2*W1_E; }
        else                     { src = Whh; dh = g_Whhh; dl = g_Whhl; o = i4 - 2*W1_E - WIH_E; }
        v = *(const float4*)(src + o);
        ushort4 h, l;
        split1(v.x, h.x, l.x); split1(v.y, h.y, l.y);
        split1(v.z, h.z, l.z); split1(v.w, h.w, l.w);
        *(ushort4*)(dh + o) = h;
        *(ushort4*)(dl + o) = l;
    }
}

/* E rows: E[r][f] = x_i[f]*x_j[f], fp16 single plane */
__global__ void k_egen(const float* __restrict__ nf, int colsel, int ppb, int full, int t0)
{
    int t4 = blockIdx.x * 256 + threadIdx.x;
    int r = t4 >> 7, q = t4 & 127;
    int b = r / ppb, p = r - b * ppb;
    int i, j;
    if (full) { i = c_pi[p]; j = c_pj[p]; } else { i = p; j = ZI; }
    const float* colb = t0 ? (nf + (size_t)(b * Nn + ZI) * Ff)
                           : (colptr(colsel) + (size_t)b * Ff);
    const float* xi = (i == ZI) ? colb : (nf + (size_t)(b * Nn + i) * Ff);
    const float* xj = (j == ZI) ? colb : (nf + (size_t)(b * Nn + j) * Ff);
    float4 a = *(const float4*)(xi + q * 4);
    float4 c2 = *(const float4*)(xj + q * 4);
    ushort4 h = make_ushort4(h1(a.x * c2.x), h1(a.y * c2.y),
                             h1(a.z * c2.z), h1(a.w * c2.w));
    *(ushort4*)(g_Ea + (size_t)r * Ff + q * 4) = h;
}

/* ------------------------------------------------------------------ */
/* K1: H1 = relu(E @ W1^T + b1), fp16 single path */
__global__ __launch_bounds__(256, 2)
void k_mlp1(const float* __restrict__ b1)
{
    extern __shared__ char dsm[];
    const int tid = threadIdx.x, lane = tid & 31, wid = tid >> 5;
    const int wm = wid & 3, wn = wid >> 2;
    const int rb = blockIdx.x, cb = blockIdx.y;

    float acc[2][8][4];
#pragma unroll
    for (int a = 0; a < 2; a++)
#pragma unroll
        for (int b = 0; b < 8; b++)
#pragma unroll
            for (int c = 0; c < 4; c++) acc[a][b][c] = 0.f;

    pipe_hf1(g_Ea + (size_t)rb * 128 * Ff,
             g_W1a + (size_t)cb * 128 * Ff,
             dsm, tid, acc);

    const int r0 = rb * 128 + wm * 32 + (lane >> 2);
    const int c0 = cb * 128 + wn * 64 + (lane & 3) * 2;
#pragma unroll
    for (int mt = 0; mt < 2; mt++)
#pragma unroll
        for (int nt = 0; nt < 8; nt++) {
            const int cc = c0 + nt * 8;
            const float bx = b1[cc], by = b1[cc + 1];
#pragma unroll
            for (int hh = 0; hh < 2; hh++) {
                const int rr = r0 + mt * 16 + hh * 8;
                float v0 = fmaxf(acc[mt][nt][hh*2+0] + bx, 0.f);
                float v1 = fmaxf(acc[mt][nt][hh*2+1] + by, 0.f);
                ushort2 h;
                h.x = h1(v0);
                h.y = h1(v1);
                *(ushort2*)(g_H1a + (size_t)rr * Ff + cc) = h;
            }
        }
}

/* ------------------------------------------------------------------ */
/* K2: adj = sum_g wout[g]*relu((H1 @ W2^T)+b2) + bout, fp16 single path */
__global__ __launch_bounds__(256, 2)
void k_mlp2(const float* __restrict__ b2, const float* __restrict__ wout,
            const float* __restrict__ boutp, float* __restrict__ adj,
            int ppb, int full)
{
    extern __shared__ char dsm[];
    __shared__ float red[128][2];

    const int tid = threadIdx.x, lane = tid & 31, wid = tid >> 5;
    const int wm = wid & 3, wn = wid >> 2;
    const int rb = blockIdx.x;

    float part[2][2] = {{0.f, 0.f}, {0.f, 0.f}};

    for (int gc = 0; gc < 4; gc++) {
        float acc[2][8][4];
#pragma unroll
        for (int a = 0; a < 2; a++)
#pragma unroll
            for (int b = 0; b < 8; b++)
#pragma unroll
                for (int c = 0; c < 4; c++) acc[a][b][c] = 0.f;

        pipe_hf1(g_H1a + (size_t)rb * 128 * Ff,
                 g_W2a + (size_t)gc * 128 * Ff,
                 dsm, tid, acc);
        __syncthreads();   /* smem reuse across gc iterations */

        const int c0 = gc * 128 + wn * 64 + (lane & 3) * 2;
#pragma unroll
        for (int mt = 0; mt < 2; mt++)
#pragma unroll
            for (int nt = 0; nt < 8; nt++) {
                const int cc = c0 + nt * 8;
                const float bx = b2[cc], by = b2[cc + 1];
                const float wx = wout[cc], wy = wout[cc + 1];
                part[mt][0] += fmaxf(acc[mt][nt][0] + bx, 0.f) * wx
                             + fmaxf(acc[mt][nt][1] + by, 0.f) * wy;
                part[mt][1] += fmaxf(acc[mt][nt][2] + bx, 0.f) * wx
                             + fmaxf(acc[mt][nt][3] + by, 0.f) * wy;
            }
    }

#pragma unroll
    for (int mt = 0; mt < 2; mt++)
#pragma unroll
        for (int h = 0; h < 2; h++) {
            float v = part[mt][h];
            v += __shfl_xor_sync(0xffffffffu, v, 1);
            v += __shfl_xor_sync(0xffffffffu, v, 2);
            part[mt][h] = v;
        }
    if ((lane & 3) == 0) {
#pragma unroll
        for (int mt = 0; mt < 2; mt++)
#pragma unroll
            for (int h = 0; h < 2; h++)
                red[wm * 32 + mt * 16 + h * 8 + (lane >> 2)][wn] = part[mt][h];
    }
    __syncthreads();

    if (tid < 128) {
        float s = red[tid][0] + red[tid][1] + boutp[0];
        int gr = rb * 128 + tid;
        int b = gr / ppb, p = gr - b * ppb;
        int i, j;
        if (full) { i = c_pi[p]; j = c_pj[p]; } else { i = p; j = ZI; }
        adj[b * 121 + i * 11 + j] = s;
        adj[b * 121 + j * 11 + i] = s;
    }
}

/* ------------------------------------------------------------------ */
/* fused: softmax(adj[b,ZI,:]) + m_base + cur/m_z splits (+ col init at t0) */
__global__ void k_attn(const float* __restrict__ nf, const float* __restrict__ adj,
                       int colsel, int t0)
{
    __shared__ float a_sh[11];
    __shared__ float azz_s;

    const int b = blockIdx.x, ch = blockIdx.y, tid = threadIdx.x;

    if (tid < 32) {
        float v = (tid < 11) ? adj[b * 121 + ZI * 11 + tid] : -1e30f;
        float m = v;
#pragma unroll
        for (int o = 16; o > 0; o >>= 1) m = fmaxf(m, __shfl_xor_sync(0xffffffffu, m, o));
        float e = (tid < 11) ? expf(v - m) : 0.f;
        float s = e;
#pragma unroll
        for (int o = 16; o > 0; o >>= 1) s += __shfl_xor_sync(0xffffffffu, s, o);
        float a = e / s;
        if (tid < 11) a_sh[tid] = a;
        if (tid == ZI) azz_s = a;
        if (ch == 0) {
            if (tid < 11) g_az[b * 12 + tid] = a;
            if (tid == ZI) g_az[b * 12 + 11] = a;
        }
    }
    __syncthreads();

    const int f = ch * 128 + tid;
    const int idx = b * Ff + f;
    float mb = 0.f;
#pragma unroll
    for (int j = 0; j < 10; j++)
        mb += a_sh[j] * nf[(size_t)(b * Nn + j) * Ff + f];
    g_mb[idx] = mb;

    float cur = t0 ? nf[(size_t)(b * Nn + ZI) * Ff + f] : colptr(colsel)[idx];
    if (t0) colptr(colsel)[idx] = cur;
    float mz = mb + azz_s * cur;
    split1(cur, g_czh[idx], g_czl[idx]);
    split1(mz,  g_mzh[idx], g_mzl[idx]);
}

/* ------------------------------------------------------------------ */
/* K5: gi = m_z @ W_ih^T (z=0) ; gh = cur @ W_hh^T (z=1) — bf16 3-term */
__global__ __launch_bounds__(256, 2)
void k_gru(void)
{
    extern __shared__ char dsm[];
    const int tid = threadIdx.x, lane = tid & 31, wid = tid >> 5;
    const int wm = wid & 3, wn = wid >> 2;
    const int rb = blockIdx.x, cb = blockIdx.y, wh = blockIdx.z;

    const unsigned short* Ah = (wh ? g_czh : g_mzh) + (size_t)rb * 128 * Ff;
    const unsigned short* Al = (wh ? g_czl : g_mzl) + (size_t)rb * 128 * Ff;
    const unsigned short* Bh = (wh ? g_Whhh : g_Wihh) + (size_t)cb * 128 * Ff;
    const unsigned short* Bl = (wh ? g_Whhl : g_Wihl) + (size_t)cb * 128 * Ff;
    float* out = wh ? g_gh : g_gi;

    float acc[2][8][4];
#pragma unroll
    for (int a = 0; a < 2; a++)
#pragma unroll
        for (int b = 0; b < 8; b++)
#pragma unroll
            for (int c = 0; c < 4; c++) acc[a][b][c] = 0.f;

    pipe_bf(Ah, Al, Bh, Bl, dsm, tid, acc);

    const int r0 = rb * 128 + wm * 32 + (lane >> 2);
    const int c0 = cb * 128 + wn * 64 + (lane & 3) * 2;
#pragma unroll
    for (int mt = 0; mt < 2; mt++)
#pragma unroll
        for (int nt = 0; nt < 8; nt++) {
            const int cc = c0 + nt * 8;
            const int rr = r0 + mt * 16;
            *(float2*)(out + (size_t)rr * G3 + cc)       = make_float2(acc[mt][nt][0], acc[mt][nt][1]);
            *(float2*)(out + (size_t)(rr + 8) * G3 + cc) = make_float2(acc[mt][nt][2], acc[mt][nt][3]);
        }
}

/* ------------------------------------------------------------------ */
/* GRU gates; produce next-step splits, or write final output directly */
__global__ void k_gate(int colsel, float* __restrict__ dst, int final_step)
{
    int idx = blockIdx.x * 256 + threadIdx.x;
    int b = idx >> 9, f = idx & 511;
    const float* cur = colptr(colsel);
    float* nxt = colptr(1 - colsel);
    const float* gib = g_gi + b * G3;
    const float* ghb = g_gh + b * G3;
    float ir = gib[f],         hr = ghb[f];
    float iz = gib[512 + f],   hz = ghb[512 + f];
    float in_ = gib[1024 + f], hn = ghb[1024 + f];
    float rr = 1.f / (1.f + expf(-(ir + hr)));
    float zz = 1.f / (1.f + expf(-(iz + hz)));
    float nn = tanhf(in_ + rr * hn);
    float h = cur[idx];
    float v = (1.f - zz) * nn + zz * h;
    nxt[idx] = v;
    if (final_step) {
        dst[idx] = v;
    } else {
        float az = g_az[b * 12 + 11];
        float mz = g_mb[idx] + az * v;
        split1(v,  g_czh[idx], g_czl[idx]);
        split1(mz, g_mzh[idx], g_mzl[idx]);
    }
}

/* ------------------------------------------------------------------ */
extern "C" void kernel_launch(void* const* d_in, const int* in_sizes, int n_in,
                              void* d_out, int out_size)
{
    const float* nf  = (const float*)d_in[0];
    const float* W1  = (const float*)d_in[1];
    const float* b1  = (const float*)d_in[2];
    const float* W2  = (const float*)d_in[3];
    const float* b2  = (const float*)d_in[4];
    const float* wo  = (const float*)d_in[5];
    const float* bo  = (const float*)d_in[6];
    const float* Wih = (const float*)d_in[7];
    const float* Whh = (const float*)d_in[8];

    float* adj    = (float*)d_out;
    float* colout = (float*)d_out + Bb * 121;

    cudaFuncSetAttribute(k_mlp1, cudaFuncAttributeMaxDynamicSharedMemorySize, DSMEM_M);
    cudaFuncSetAttribute(k_mlp2, cudaFuncAttributeMaxDynamicSharedMemorySize, DSMEM_M);
    cudaFuncSetAttribute(k_gru,  cudaFuncAttributeMaxDynamicSharedMemorySize, DSMEM_G);

    k_split_all<<<(2 * W1_E + 2 * WIH_E) / 1024, 256>>>(W1, W2, Wih, Whh);

    int sel = 0;
    for (int t = 0; t < 3; t++) {
        const int rows = (t == 0) ? R0 : R1;
        const int ppb  = (t == 0) ? PPF : Nn;
        const int full = (t == 0) ? 1 : 0;
        const int t0   = (t == 0) ? 1 : 0;
        k_egen<<<(rows * (Ff / 4)) / 256, 256>>>(nf, sel, ppb, full, t0);
        k_mlp1<<<dim3(rows / 128, 4), 256, DSMEM_M>>>(b1);
        k_mlp2<<<rows / 128, 256, DSMEM_M>>>(b2, wo, bo, adj, ppb, full);
        k_attn<<<dim3(Bb, 4), 128>>>(nf, adj, sel, t0);
        for (int s = 0; s < 3; s++) {
            const int fin = (t == 2 && s == 2) ? 1 : 0;
            k_gru<<<dim3(Bb / 128, G3 / 128, 2), 256, DSMEM_G>>>();
            k_gate<<<(Bb * Ff) / 256, 256>>>(sel, colout, fin);
            sel = 1 - sel;
        }
    }
}